// round 11
// baseline (speedup 1.0000x reference)
#include <cuda_runtime.h>
#include <cuda_bf16.h>
#include <cuda_fp16.h>
#include <math.h>
#include <math_constants.h>
#include <stdint.h>

// Problem constants
#define BSZ 2
#define TSEQ 2048
#define CDIM 1024
#define NHEAD 16
#define DHEAD 64
#define MROWS (BSZ * TSEQ)          // 4096
#define QKVCOLS (3 * CDIM)          // 3072

// ---------------------------------------------------------------------------
// Scratch
// ---------------------------------------------------------------------------
__device__ float g_qkv[(size_t)MROWS * QKVCOLS];
// fp16 fragment-order operands (uint4 = one lane's 4 regs of an m16n8k16 frag)
__device__ uint4 g_xf[(size_t)(MROWS / 16) * (CDIM / 16) * 32];
__device__ uint4 g_waf[(size_t)(CDIM / 16) * (QKVCOLS / 16) * 32];
__device__ uint4 g_wpf[(size_t)(CDIM / 16) * (CDIM / 16) * 32];
__device__ uint4 g_yf[(size_t)(MROWS / 16) * (CDIM / 16) * 32];
__device__ __nv_bfloat16 g_qh[(size_t)BSZ * NHEAD * TSEQ * DHEAD];
__device__ __nv_bfloat16 g_ql[(size_t)BSZ * NHEAD * TSEQ * DHEAD];
__device__ __nv_bfloat16 g_kh[(size_t)BSZ * NHEAD * TSEQ * DHEAD];
__device__ __nv_bfloat16 g_kl[(size_t)BSZ * NHEAD * TSEQ * DHEAD];
__device__ __nv_bfloat16 g_vth[(size_t)BSZ * NHEAD * DHEAD * TSEQ];  // [bh][d][t]
__device__ __nv_bfloat16 g_vtl[(size_t)BSZ * NHEAD * DHEAD * TSEQ];
__device__ float2 g_rope[TSEQ * (DHEAD / 2)];

// ---------------------------------------------------------------------------
// RoPE table
// ---------------------------------------------------------------------------
__global__ void build_rope_kernel(float2* __restrict__ table) {
    int i = blockIdx.x * blockDim.x + threadIdx.x;
    if (i >= TSEQ * 32) return;
    int t = i >> 5;
    int j = i & 31;
    double inv = pow(10000.0, -(double)j / 32.0);
    double ang = (double)t * inv;
    table[i] = make_float2((float)cos(ang), (float)sin(ang));
}

// ---------------------------------------------------------------------------
// Math helpers
// ---------------------------------------------------------------------------
__device__ __forceinline__ float ex2f(float x) {
    float r;
    asm("ex2.approx.ftz.f32 %0, %1;" : "=f"(r) : "f"(x));
    return r;
}
__device__ __forceinline__ uint32_t h2u(__half2 h) {
    return *reinterpret_cast<uint32_t*>(&h);
}
__device__ __forceinline__ void mma_fp16(float c[4], uint32_t a0, uint32_t a1,
                                         uint32_t a2, uint32_t a3,
                                         uint32_t b0, uint32_t b1) {
    asm volatile(
        "mma.sync.aligned.m16n8k16.row.col.f32.f16.f16.f32 "
        "{%0,%1,%2,%3}, {%4,%5,%6,%7}, {%8,%9}, {%0,%1,%2,%3};\n"
        : "+f"(c[0]), "+f"(c[1]), "+f"(c[2]), "+f"(c[3])
        : "r"(a0), "r"(a1), "r"(a2), "r"(a3), "r"(b0), "r"(b1));
}
__device__ __forceinline__ void mma_bf16(float c[4], uint32_t a0, uint32_t a1,
                                         uint32_t a2, uint32_t a3,
                                         uint32_t b0, uint32_t b1) {
    asm volatile(
        "mma.sync.aligned.m16n8k16.row.col.f32.bf16.bf16.f32 "
        "{%0,%1,%2,%3}, {%4,%5,%6,%7}, {%8,%9}, {%0,%1,%2,%3};\n"
        : "+f"(c[0]), "+f"(c[1]), "+f"(c[2]), "+f"(c[3])
        : "r"(a0), "r"(a1), "r"(a2), "r"(a3), "r"(b0), "r"(b1));
}
__device__ __forceinline__ void ldsm_x4(uint32_t& r0, uint32_t& r1,
                                        uint32_t& r2, uint32_t& r3,
                                        uint32_t addr) {
    asm volatile(
        "ldmatrix.sync.aligned.m8n8.x4.shared.b16 {%0,%1,%2,%3}, [%4];"
        : "=r"(r0), "=r"(r1), "=r"(r2), "=r"(r3) : "r"(addr));
}
__device__ __forceinline__ void packsplit2(float p0, float p1,
                                           uint32_t& hi, uint32_t& lo) {
    __nv_bfloat162 h = __floats2bfloat162_rn(p0, p1);
    float2 f = __bfloat1622float2(h);
    __nv_bfloat162 l = __floats2bfloat162_rn(p0 - f.x, p1 - f.y);
    hi = *reinterpret_cast<uint32_t*>(&h);
    lo = *reinterpret_cast<uint32_t*>(&l);
}
__device__ __forceinline__ uint32_t smem_u32(const void* p) {
    uint32_t a;
    asm("{ .reg .u64 t; cvta.to.shared.u64 t, %1; cvt.u32.u64 %0, t; }"
        : "=r"(a) : "l"(p));
    return a;
}
__device__ __forceinline__ void cp16(uint32_t smem, const void* g) {
    asm volatile("cp.async.ca.shared.global [%0], [%1], 16;"
                 :: "r"(smem), "l"(g) : "memory");
}
#define CP_COMMIT() asm volatile("cp.async.commit_group;" ::: "memory")
#define CP_WAIT0() asm volatile("cp.async.wait_group 0;" ::: "memory")
#define CP_WAIT1() asm volatile("cp.async.wait_group 1;" ::: "memory")
#define CP_WAIT2() asm volatile("cp.async.wait_group 2;" ::: "memory")

// ---------------------------------------------------------------------------
// fp16 A-fragment reorder: [M][K] fp32 -> [M/16][K/16][32] uint4
// lane (g,tig): u0={A[g][2t],A[g][2t+1]} u1={A[g+8][...]}
//               u2={A[g][2t+8],[2t+9]}  u3={A[g+8][2t+8],[2t+9]}  (t=tig)
// ---------------------------------------------------------------------------
__global__ void afrag16_kernel(const float* __restrict__ in,
                               uint4* __restrict__ out, int K) {
    int idx = blockIdx.x * 256 + threadIdx.x;
    int lane = idx & 31;
    int blk = idx >> 5;
    int KB = K >> 4;
    int cb = blk % KB, rb = blk / KB;
    int g = lane >> 2, tig = lane & 3;
    const float* p = in + (size_t)(rb * 16 + g) * K + cb * 16 + 2 * tig;
    const size_t r8 = (size_t)8 * K;
    uint4 v;
    v.x = h2u(__floats2half2_rn(p[0], p[1]));
    v.y = h2u(__floats2half2_rn(p[r8], p[r8 + 1]));
    v.z = h2u(__floats2half2_rn(p[8], p[9]));
    v.w = h2u(__floats2half2_rn(p[r8 + 8], p[r8 + 9]));
    out[idx] = v;
}

// ---------------------------------------------------------------------------
// fp16 paired B-fragment reorder: [K][N] fp32 -> [K/16][N/16][32] uint4
// lane (g,tig): u0={B[2t][g],B[2t+1][g]} u1={B[2t+8][g],B[2t+9][g]}
//               u2,u3 = same with n -> 8+g
// ---------------------------------------------------------------------------
__global__ void bfrag16_kernel(const float* __restrict__ in,
                               uint4* __restrict__ out, int N) {
    int idx = blockIdx.x * 256 + threadIdx.x;
    int lane = idx & 31;
    int blk = idx >> 5;
    int NB = N >> 4;
    int nbp = blk % NB, kb = blk / NB;
    int g = lane >> 2, tig = lane & 3;
    const float* p = in + (size_t)(kb * 16 + 2 * tig) * N + nbp * 16 + g;
    const size_t sN = (size_t)N;
    uint4 v;
    v.x = h2u(__floats2half2_rn(p[0], p[sN]));
    v.y = h2u(__floats2half2_rn(p[8 * sN], p[9 * sN]));
    v.z = h2u(__floats2half2_rn(p[8], p[sN + 8]));
    v.w = h2u(__floats2half2_rn(p[8 * sN + 8], p[9 * sN + 8]));
    out[idx] = v;
}

// ---------------------------------------------------------------------------
// FP16 GEMM v5: fragment-order operands, 3-stage cp.async, m16n8k16.
// C[M,N] = A@B + bias. 128x128x32 tile, 256 thr (8 warps, 2m x 4n).
// Smem: 3 stages x (A 8KB + B 8KB) = 48KB.
// ---------------------------------------------------------------------------
#define GEMM_SMEM_BYTES 49152

__global__ __launch_bounds__(256, 2)
void gemm_fp16_kernel(const uint4* __restrict__ Af, const uint4* __restrict__ Bf,
                      const float* __restrict__ bias, float* __restrict__ C,
                      int M, int N, int K) {
    extern __shared__ char smg[];
    const uint32_t smb = smem_u32(smg);
    const int tid = threadIdx.x;
    const int lane = tid & 31;
    const int warp = tid >> 5;
    const int wm = warp >> 2;      // 0..1
    const int wn = warp & 3;       // 0..3
    const int g = lane >> 2;
    const int tig = lane & 3;
    const int row0 = blockIdx.y * 128;
    const int col0 = blockIdx.x * 128;
    const int KB16 = K >> 4;
    const int NB16 = N >> 4;
    const int rb0 = row0 >> 4;
    const int nbp0 = col0 >> 4;

    float acc[4][4][4];
#pragma unroll
    for (int im = 0; im < 4; im++)
#pragma unroll
        for (int in = 0; in < 4; in++)
#pragma unroll
            for (int r = 0; r < 4; r++) acc[im][in][r] = 0.0f;

    // loader maps: per stage A 512 units, B 512 units; 2+2 per thread
    int a_rblk[2], a_kblk[2], a_l[2];
    int b_blk[2], b_kblk[2], b_nbp[2], b_l[2];
#pragma unroll
    for (int s = 0; s < 2; s++) {
        int u = tid + s * 256;          // 0..511
        int ablk = u >> 5;              // 0..15
        a_rblk[s] = ablk >> 1;
        a_kblk[s] = ablk & 1;
        a_l[s] = u & 31;
        b_blk[s] = u >> 5;              // kblk*8 + nbp
        b_kblk[s] = u >> 8;             // 0..1
        b_nbp[s] = (u >> 5) & 7;
        b_l[s] = u & 31;
    }

    const int nT = K / 32;

#define GEMM_ISSUE(tt) do {                                                    \
        const int kbg = (tt) * 2;                                              \
        const int st = (tt) % 3;                                               \
        const uint32_t ao = (uint32_t)(st * 8192);                             \
        const uint32_t bo = 24576u + (uint32_t)(st * 8192);                    \
        _Pragma("unroll")                                                      \
        for (int s = 0; s < 2; s++) {                                          \
            cp16(smb + ao + (uint32_t)((a_rblk[s] * 2 + a_kblk[s]) * 512 + a_l[s] * 16), \
                 Af + (((size_t)(rb0 + a_rblk[s]) * KB16 + kbg + a_kblk[s]) << 5) + a_l[s]); \
            cp16(smb + bo + (uint32_t)(b_blk[s] * 512 + b_l[s] * 16),          \
                 Bf + (((size_t)(kbg + b_kblk[s]) * NB16 + nbp0 + b_nbp[s]) << 5) + b_l[s]); \
        }                                                                      \
        CP_COMMIT();                                                           \
    } while (0)

    GEMM_ISSUE(0);
    GEMM_ISSUE(1);

    for (int t = 0; t < nT; t++) {
        if (t + 2 < nT) {
            GEMM_ISSUE(t + 2);
            CP_WAIT2();
        } else if (t + 1 < nT) {
            CP_WAIT1();
        } else {
            CP_WAIT0();
        }
        __syncthreads();

        const char* As = smg + (t % 3) * 8192;
        const char* Bs = smg + 24576 + (t % 3) * 8192;

#pragma unroll
        for (int kk = 0; kk < 2; kk++) {
            uint4 af[4];
#pragma unroll
            for (int im = 0; im < 4; im++)
                af[im] = *(const uint4*)(As + ((wm * 4 + im) * 2 + kk) * 512 + lane * 16);
            uint4 b4[2];
#pragma unroll
            for (int p = 0; p < 2; p++)
                b4[p] = *(const uint4*)(Bs + (kk * 8 + wn * 2 + p) * 512 + lane * 16);
#pragma unroll
            for (int im = 0; im < 4; im++) {
#pragma unroll
                for (int p = 0; p < 2; p++) {
                    mma_fp16(acc[im][2 * p], af[im].x, af[im].y, af[im].z, af[im].w,
                             b4[p].x, b4[p].y);
                    mma_fp16(acc[im][2 * p + 1], af[im].x, af[im].y, af[im].z, af[im].w,
                             b4[p].z, b4[p].w);
                }
            }
        }
        __syncthreads();
    }

    // epilogue: rows g + {0,8}, cols 2*tig + {0,1}
#pragma unroll
    for (int im = 0; im < 4; im++) {
        int r = row0 + wm * 64 + im * 16 + g;
#pragma unroll
        for (int in = 0; in < 4; in++) {
            int c = col0 + wn * 32 + in * 8 + tig * 2;
            float b0 = bias[c], b1 = bias[c + 1];
            float2 v0 = make_float2(acc[im][in][0] + b0, acc[im][in][1] + b1);
            float2 v1 = make_float2(acc[im][in][2] + b0, acc[im][in][3] + b1);
            *(float2*)&C[(size_t)r * N + c] = v0;
            *(float2*)&C[(size_t)(r + 8) * N + c] = v1;
        }
    }
#undef GEMM_ISSUE
}

// ---------------------------------------------------------------------------
// RoPE + scatter + splits + V transpose (unchanged)
// ---------------------------------------------------------------------------
__global__ __launch_bounds__(256)
void rope_scatter_split_kernel(const float* __restrict__ qkv,
                               const float2* __restrict__ rope,
                               __nv_bfloat16* __restrict__ qh,
                               __nv_bfloat16* __restrict__ ql,
                               __nv_bfloat16* __restrict__ kh,
                               __nv_bfloat16* __restrict__ kl,
                               __nv_bfloat16* __restrict__ vth,
                               __nv_bfloat16* __restrict__ vtl) {
    __shared__ __nv_bfloat16 vsh[64][66];
    __shared__ __nv_bfloat16 vsl[64][66];

    int bh = blockIdx.y;
    int tb = blockIdx.x * 64;
    int b = bh >> 4;
    int h = bh & 15;
    int tid = threadIdx.x;

    const float SCL = 0.125f * 1.4426950408889634f;

#pragma unroll
    for (int e = 0; e < 16; e++) {
        int idx = tid + e * 256;
        int tl = idx >> 6;
        int d = idx & 63;
        int t = tb + tl;
        size_t base = (size_t)(b * TSEQ + t) * QKVCOLS + h * DHEAD;
        float2 cs = rope[t * 32 + (d & 31)];

        float qv = qkv[base + d];
        float kv = qkv[base + CDIM + d];
        float vv = qkv[base + 2 * CDIM + d];
        int dp = (d < 32) ? d + 32 : d - 32;
        float sgn = (d < 32) ? -1.0f : 1.0f;
        float qr = qkv[base + dp];
        float kr = qkv[base + CDIM + dp];

        float qrot = (qv * cs.x + sgn * qr * cs.y) * SCL;
        float krot = kv * cs.x + sgn * kr * cs.y;

        size_t o = ((size_t)bh * TSEQ + t) * DHEAD + d;
        __nv_bfloat16 qhv = __float2bfloat16(qrot);
        __nv_bfloat16 khv = __float2bfloat16(krot);
        qh[o] = qhv;
        ql[o] = __float2bfloat16(qrot - __bfloat162float(qhv));
        kh[o] = khv;
        kl[o] = __float2bfloat16(krot - __bfloat162float(khv));

        __nv_bfloat16 vhv = __float2bfloat16(vv);
        vsh[d][tl] = vhv;
        vsl[d][tl] = __float2bfloat16(vv - __bfloat162float(vhv));
    }
    __syncthreads();
#pragma unroll
    for (int e = 0; e < 16; e++) {
        int idx = tid + e * 256;
        int d = idx >> 6;
        int tl = idx & 63;
        size_t o = ((size_t)bh * DHEAD + d) * TSEQ + tb + tl;
        vth[o] = vsh[d][tl];
        vtl[o] = vsl[d][tl];
    }
}

// ---------------------------------------------------------------------------
// Flash attention v6: ldmatrix loads (round 9 core); epilogue writes y as
// fp16 A-fragments (4x STG.128), feeding the fp16 proj GEMM directly.
// ---------------------------------------------------------------------------
#define FRS 144
#define OFF_KH 0
#define OFF_KL 9216
#define OFF_VTH 18432
#define OFF_VTL 27648
#define BUFB 36864
#define FLASH_SMEM_BYTES (2 * BUFB)

#define NEGBIG (-1e30f)

__global__ __launch_bounds__(128, 3)
void flash_mma_kernel(const __nv_bfloat16* __restrict__ QH,
                      const __nv_bfloat16* __restrict__ QL,
                      const __nv_bfloat16* __restrict__ KH,
                      const __nv_bfloat16* __restrict__ KL,
                      const __nv_bfloat16* __restrict__ VTH,
                      const __nv_bfloat16* __restrict__ VTL) {
    extern __shared__ char smc[];
    const uint32_t smb = smem_u32(smc);

    int bh = blockIdx.y;
    int qt = gridDim.x - 1 - blockIdx.x;
    int q0 = qt * 64;

    int tid = threadIdx.x;
    int lane = tid & 31;
    int w = tid >> 5;
    int g = lane >> 2;
    int tig = lane & 3;
    const int r0 = w * 16 + g;

    const int jj = lane & 7;
    const uint32_t ldsm_base =
        (uint32_t)((jj + ((lane >> 4) & 1) * 8) * FRS + ((lane >> 3) & 1) * 16);

    const __nv_bfloat16* KHg = KH + (size_t)bh * TSEQ * DHEAD;
    const __nv_bfloat16* KLg = KL + (size_t)bh * TSEQ * DHEAD;
    const __nv_bfloat16* VTHg = VTH + (size_t)bh * DHEAD * TSEQ;
    const __nv_bfloat16* VTLg = VTL + (size_t)bh * DHEAD * TSEQ;

    {
#pragma unroll
        for (int s = 0; s < 4; s++) {
            int f = tid + s * 128;
            int r = f >> 3;
            int c = (f & 7) * 8;
            uint32_t ro = (uint32_t)(r * FRS + c * 2);
            cp16(smb + OFF_KH + ro, KHg + (size_t)r * DHEAD + c);
            cp16(smb + OFF_KL + ro, KLg + (size_t)r * DHEAD + c);
            cp16(smb + OFF_VTH + ro, VTHg + (size_t)r * TSEQ + c);
            cp16(smb + OFF_VTL + ro, VTLg + (size_t)r * TSEQ + c);
        }
        CP_COMMIT();
    }

    uint32_t qah[4][4], qal[4][4];
    {
        const __nv_bfloat16* Qhg = QH + ((size_t)bh * TSEQ + q0 + r0) * DHEAD;
        const __nv_bfloat16* Qlg = QL + ((size_t)bh * TSEQ + q0 + r0) * DHEAD;
#pragma unroll
        for (int ks = 0; ks < 4; ks++) {
            int c0 = ks * 16 + 2 * tig;
            qah[ks][0] = *(const uint32_t*)(Qhg + c0);
            qah[ks][1] = *(const uint32_t*)(Qhg + 8 * DHEAD + c0);
            qah[ks][2] = *(const uint32_t*)(Qhg + c0 + 8);
            qah[ks][3] = *(const uint32_t*)(Qhg + 8 * DHEAD + c0 + 8);
            qal[ks][0] = *(const uint32_t*)(Qlg + c0);
            qal[ks][1] = *(const uint32_t*)(Qlg + 8 * DHEAD + c0);
            qal[ks][2] = *(const uint32_t*)(Qlg + c0 + 8);
            qal[ks][3] = *(const uint32_t*)(Qlg + 8 * DHEAD + c0 + 8);
        }
    }

    float oacc[8][4];
#pragma unroll
    for (int db = 0; db < 8; db++)
#pragma unroll
        for (int r = 0; r < 4; r++) oacc[db][r] = 0.0f;
    float m0 = NEGBIG, m1 = NEGBIG, l0 = 0.0f, l1 = 0.0f;

    for (int jt = 0; jt <= qt; jt++) {
        CP_WAIT0();
        __syncthreads();

        if (jt < qt) {
            int k0n = (jt + 1) * 64;
            uint32_t nb_ = smb + ((jt + 1) & 1) * BUFB;
#pragma unroll
            for (int s = 0; s < 4; s++) {
                int f = tid + s * 128;
                int r = f >> 3;
                int c = (f & 7) * 8;
                uint32_t ro = (uint32_t)(r * FRS + c * 2);
                cp16(nb_ + OFF_KH + ro, KHg + (size_t)(k0n + r) * DHEAD + c);
                cp16(nb_ + OFF_KL + ro, KLg + (size_t)(k0n + r) * DHEAD + c);
                cp16(nb_ + OFF_VTH + ro, VTHg + (size_t)r * TSEQ + k0n + c);
                cp16(nb_ + OFF_VTL + ro, VTLg + (size_t)r * TSEQ + k0n + c);
            }
            CP_COMMIT();
        }

        const uint32_t bufa = smb + (jt & 1) * BUFB + ldsm_base;

        float sacc[8][4];
#pragma unroll
        for (int nb = 0; nb < 8; nb++)
#pragma unroll
            for (int r = 0; r < 4; r++) sacc[nb][r] = 0.0f;

#pragma unroll
        for (int ks = 0; ks < 4; ks++) {
            const uint32_t ko = (uint32_t)(ks * 32);
#pragma unroll
            for (int nbp = 0; nbp < 4; nbp++) {
                const uint32_t ba = bufa + (uint32_t)(nbp * 16 * FRS) + ko;
                uint32_t h0, h1, h2, h3, e0, e1, e2, e3;
                ldsm_x4(h0, h1, h2, h3, ba + OFF_KH);
                ldsm_x4(e0, e1, e2, e3, ba + OFF_KL);
                mma_bf16(sacc[2 * nbp], qah[ks][0], qah[ks][1], qah[ks][2], qah[ks][3], h0, h1);
                mma_bf16(sacc[2 * nbp], qah[ks][0], qah[ks][1], qah[ks][2], qah[ks][3], e0, e1);
                mma_bf16(sacc[2 * nbp], qal[ks][0], qal[ks][1], qal[ks][2], qal[ks][3], h0, h1);
                mma_bf16(sacc[2 * nbp + 1], qah[ks][0], qah[ks][1], qah[ks][2], qah[ks][3], h2, h3);
                mma_bf16(sacc[2 * nbp + 1], qah[ks][0], qah[ks][1], qah[ks][2], qah[ks][3], e2, e3);
                mma_bf16(sacc[2 * nbp + 1], qal[ks][0], qal[ks][1], qal[ks][2], qal[ks][3], h2, h3);
            }
        }

        if (jt == qt) {
#pragma unroll
            for (int nb = 0; nb < 8; nb++) {
                int c0 = nb * 8 + 2 * tig;
#pragma unroll
                for (int e = 0; e < 2; e++) {
                    if (c0 + e > r0) sacc[nb][e] = NEGBIG;
                    if (c0 + e > r0 + 8) sacc[nb][2 + e] = NEGBIG;
                }
            }
        }

        float tm0 = NEGBIG, tm1 = NEGBIG;
#pragma unroll
        for (int nb = 0; nb < 8; nb++) {
            tm0 = fmaxf(tm0, fmaxf(sacc[nb][0], sacc[nb][1]));
            tm1 = fmaxf(tm1, fmaxf(sacc[nb][2], sacc[nb][3]));
        }
        tm0 = fmaxf(tm0, __shfl_xor_sync(0xffffffffu, tm0, 1));
        tm0 = fmaxf(tm0, __shfl_xor_sync(0xffffffffu, tm0, 2));
        tm1 = fmaxf(tm1, __shfl_xor_sync(0xffffffffu, tm1, 1));
        tm1 = fmaxf(tm1, __shfl_xor_sync(0xffffffffu, tm1, 2));

        float mn0 = fmaxf(m0, tm0);
        float mn1 = fmaxf(m1, tm1);
        float corr0 = ex2f(m0 - mn0);
        float corr1 = ex2f(m1 - mn1);
        float rs0 = 0.0f, rs1 = 0.0f;
#pragma unroll
        for (int nb = 0; nb < 8; nb++) {
            sacc[nb][0] = ex2f(sacc[nb][0] - mn0);
            sacc[nb][1] = ex2f(sacc[nb][1] - mn0);
            sacc[nb][2] = ex2f(sacc[nb][2] - mn1);
            sacc[nb][3] = ex2f(sacc[nb][3] - mn1);
            rs0 += sacc[nb][0] + sacc[nb][1];
            rs1 += sacc[nb][2] + sacc[nb][3];
        }
        rs0 += __shfl_xor_sync(0xffffffffu, rs0, 1);
        rs0 += __shfl_xor_sync(0xffffffffu, rs0, 2);
        rs1 += __shfl_xor_sync(0xffffffffu, rs1, 1);
        rs1 += __shfl_xor_sync(0xffffffffu, rs1, 2);

        l0 = l0 * corr0 + rs0;
        l1 = l1 * corr1 + rs1;
        m0 = mn0;
        m1 = mn1;
#pragma unroll
        for (int db = 0; db < 8; db++) {
            oacc[db][0] *= corr0;
            oacc[db][1] *= corr0;
            oacc[db][2] *= corr1;
            oacc[db][3] *= corr1;
        }

#pragma unroll
        for (int ks = 0; ks < 4; ks++) {
            uint32_t ph[4], pl[4];
            packsplit2(sacc[2 * ks][0], sacc[2 * ks][1], ph[0], pl[0]);
            packsplit2(sacc[2 * ks][2], sacc[2 * ks][3], ph[1], pl[1]);
            packsplit2(sacc[2 * ks + 1][0], sacc[2 * ks + 1][1], ph[2], pl[2]);
            packsplit2(sacc[2 * ks + 1][2], sacc[2 * ks + 1][3], ph[3], pl[3]);
            const uint32_t ko = (uint32_t)(ks * 32);
#pragma unroll
            for (int dbp = 0; dbp < 4; dbp++) {
                const uint32_t ba = bufa + (uint32_t)(dbp * 16 * FRS) + ko;
                uint32_t h0, h1, h2, h3, e0, e1, e2, e3;
                ldsm_x4(h0, h1, h2, h3, ba + OFF_VTH);
                ldsm_x4(e0, e1, e2, e3, ba + OFF_VTL);
                mma_bf16(oacc[2 * dbp], ph[0], ph[1], ph[2], ph[3], h0, h1);
                mma_bf16(oacc[2 * dbp], ph[0], ph[1], ph[2], ph[3], e0, e1);
                mma_bf16(oacc[2 * dbp], pl[0], pl[1], pl[2], pl[3], h0, h1);
                mma_bf16(oacc[2 * dbp + 1], ph[0], ph[1], ph[2], ph[3], h2, h3);
                mma_bf16(oacc[2 * dbp + 1], ph[0], ph[1], ph[2], ph[3], e2, e3);
                mma_bf16(oacc[2 * dbp + 1], pl[0], pl[1], pl[2], pl[3], h2, h3);
            }
        }
    }

    // ---- finalize: write y as fp16 A-fragments (uint4 per lane) ----
    // yf layout [M/16][CDIM/16=64][32]. This warp: row-block rb, lane holds
    // rows g,g+8 / cols 2tig(+1),(+8,+9) of block cb = h*4 + (db>>1).
    float inv0 = 1.0f / l0;
    float inv1 = 1.0f / l1;
    int b = bh >> 4;
    int h = bh & 15;
    const size_t rb = (size_t)((b * TSEQ + q0) >> 4) + w;
#pragma unroll
    for (int dbp = 0; dbp < 4; dbp++) {
        int cb = h * 4 + dbp;
        uint4 v;
        v.x = h2u(__floats2half2_rn(oacc[2 * dbp][0] * inv0, oacc[2 * dbp][1] * inv0));
        v.y = h2u(__floats2half2_rn(oacc[2 * dbp][2] * inv1, oacc[2 * dbp][3] * inv1));
        v.z = h2u(__floats2half2_rn(oacc[2 * dbp + 1][0] * inv0, oacc[2 * dbp + 1][1] * inv0));
        v.w = h2u(__floats2half2_rn(oacc[2 * dbp + 1][2] * inv1, oacc[2 * dbp + 1][3] * inv1));
        g_yf[(rb * 64 + cb) * 32 + lane] = v;
    }
}

// ---------------------------------------------------------------------------
// Launch
// ---------------------------------------------------------------------------
extern "C" void kernel_launch(void* const* d_in, const int* in_sizes, int n_in,
                              void* d_out, int out_size) {
    const float* x      = (const float*)d_in[0];
    const float* w_attn = (const float*)d_in[1];
    const float* b_attn = (const float*)d_in[2];
    const float* w_proj = (const float*)d_in[3];
    const float* b_proj = (const float*)d_in[4];
    float* out = (float*)d_out;

    float* qkv;
    uint4 *xf, *waf, *wpf, *yf;
    float2* rope;
    __nv_bfloat16 *qh, *ql, *kh, *kl, *vth, *vtl;
    cudaGetSymbolAddress((void**)&qkv, g_qkv);
    cudaGetSymbolAddress((void**)&xf, g_xf);
    cudaGetSymbolAddress((void**)&waf, g_waf);
    cudaGetSymbolAddress((void**)&wpf, g_wpf);
    cudaGetSymbolAddress((void**)&yf, g_yf);
    cudaGetSymbolAddress((void**)&qh, g_qh);
    cudaGetSymbolAddress((void**)&ql, g_ql);
    cudaGetSymbolAddress((void**)&kh, g_kh);
    cudaGetSymbolAddress((void**)&kl, g_kl);
    cudaGetSymbolAddress((void**)&vth, g_vth);
    cudaGetSymbolAddress((void**)&vtl, g_vtl);
    cudaGetSymbolAddress((void**)&rope, g_rope);

    cudaFuncSetAttribute(gemm_fp16_kernel,
                         cudaFuncAttributeMaxDynamicSharedMemorySize,
                         GEMM_SMEM_BYTES);
    cudaFuncSetAttribute(flash_mma_kernel,
                         cudaFuncAttributeMaxDynamicSharedMemorySize,
                         FLASH_SMEM_BYTES);

    build_rope_kernel<<<(TSEQ * 32 + 255) / 256, 256>>>(rope);

    // fp16 fragment-order prep
    afrag16_kernel<<<(MROWS / 16) * (CDIM / 16) * 32 / 256, 256>>>(x, xf, CDIM);
    bfrag16_kernel<<<(CDIM / 16) * (QKVCOLS / 16) * 32 / 256, 256>>>(w_attn, waf, QKVCOLS);
    bfrag16_kernel<<<(CDIM / 16) * (CDIM / 16) * 32 / 256, 256>>>(w_proj, wpf, CDIM);

    // QKV GEMM (fp16 m16n8k16)
    gemm_fp16_kernel<<<dim3(QKVCOLS / 128, MROWS / 128), 256, GEMM_SMEM_BYTES>>>(
        xf, waf, b_attn, qkv, MROWS, QKVCOLS, CDIM);

    // RoPE + scatter + splits + V transpose
    rope_scatter_split_kernel<<<dim3(TSEQ / 64, BSZ * NHEAD), 256>>>(
        qkv, rope, qh, ql, kh, kl, vth, vtl);

    // Flash attention (writes yf directly as fp16 A-fragments)
    flash_mma_kernel<<<dim3(TSEQ / 64, BSZ * NHEAD), 128, FLASH_SMEM_BYTES>>>(
        qh, ql, kh, kl, vth, vtl);

    // Output projection (fp16 m16n8k16)
    gemm_fp16_kernel<<<dim3(CDIM / 128, MROWS / 128), 256, GEMM_SMEM_BYTES>>>(
        yf, wpf, b_proj, out, MROWS, CDIM, CDIM);
}

// round 12
// speedup vs baseline: 1.3759x; 1.3759x over previous
#include <cuda_runtime.h>
#include <cuda_bf16.h>
#include <cuda_fp16.h>
#include <math.h>
#include <math_constants.h>
#include <stdint.h>

// Problem constants
#define BSZ 2
#define TSEQ 2048
#define CDIM 1024
#define NHEAD 16
#define DHEAD 64
#define MROWS (BSZ * TSEQ)          // 4096
#define QKVCOLS (3 * CDIM)          // 3072

// ---------------------------------------------------------------------------
// Scratch
// ---------------------------------------------------------------------------
__device__ float g_qkv[(size_t)MROWS * QKVCOLS];
__device__ float g_xf[(size_t)MROWS * CDIM];          // x, A-frag order, tf32
__device__ float g_waf[(size_t)CDIM * QKVCOLS];       // w_attn, B-frag order, tf32
__device__ float g_wpf[(size_t)CDIM * CDIM];          // w_proj, B-frag order, tf32
__device__ float g_yf[(size_t)MROWS * CDIM];          // y, A-frag order, tf32
__device__ __nv_bfloat16 g_qh[(size_t)BSZ * NHEAD * TSEQ * DHEAD];
__device__ __nv_bfloat16 g_ql[(size_t)BSZ * NHEAD * TSEQ * DHEAD];
__device__ __nv_bfloat16 g_kh[(size_t)BSZ * NHEAD * TSEQ * DHEAD];
__device__ __nv_bfloat16 g_kl[(size_t)BSZ * NHEAD * TSEQ * DHEAD];
__device__ __half g_vt[(size_t)BSZ * NHEAD * DHEAD * TSEQ];   // [bh][d][t], fp16
__device__ float g_y[(size_t)MROWS * CDIM];
__device__ float2 g_rope[TSEQ * (DHEAD / 2)];

// ---------------------------------------------------------------------------
// RoPE table
// ---------------------------------------------------------------------------
__global__ void build_rope_kernel(float2* __restrict__ table) {
    int i = blockIdx.x * blockDim.x + threadIdx.x;
    if (i >= TSEQ * 32) return;
    int t = i >> 5;
    int j = i & 31;
    double inv = pow(10000.0, -(double)j / 32.0);
    double ang = (double)t * inv;
    table[i] = make_float2((float)cos(ang), (float)sin(ang));
}

// ---------------------------------------------------------------------------
// Math helpers
// ---------------------------------------------------------------------------
__device__ __forceinline__ uint32_t f2tf32(float x) {
    uint32_t r;
    asm("cvt.rna.tf32.f32 %0, %1;" : "=r"(r) : "f"(x));
    return r;
}
__device__ __forceinline__ float tf32f(float x) {
    return __uint_as_float(f2tf32(x));
}
__device__ __forceinline__ float ex2f(float x) {
    float r;
    asm("ex2.approx.ftz.f32 %0, %1;" : "=f"(r) : "f"(x));
    return r;
}
__device__ __forceinline__ uint32_t h2u(__half2 h) {
    return *reinterpret_cast<uint32_t*>(&h);
}
__device__ __forceinline__ void mma_tf32(float c[4], uint32_t a0, uint32_t a1,
                                         uint32_t a2, uint32_t a3,
                                         uint32_t b0, uint32_t b1) {
    asm volatile(
        "mma.sync.aligned.m16n8k8.row.col.f32.tf32.tf32.f32 "
        "{%0,%1,%2,%3}, {%4,%5,%6,%7}, {%8,%9}, {%0,%1,%2,%3};\n"
        : "+f"(c[0]), "+f"(c[1]), "+f"(c[2]), "+f"(c[3])
        : "r"(a0), "r"(a1), "r"(a2), "r"(a3), "r"(b0), "r"(b1));
}
__device__ __forceinline__ void mma_bf16(float c[4], uint32_t a0, uint32_t a1,
                                         uint32_t a2, uint32_t a3,
                                         uint32_t b0, uint32_t b1) {
    asm volatile(
        "mma.sync.aligned.m16n8k16.row.col.f32.bf16.bf16.f32 "
        "{%0,%1,%2,%3}, {%4,%5,%6,%7}, {%8,%9}, {%0,%1,%2,%3};\n"
        : "+f"(c[0]), "+f"(c[1]), "+f"(c[2]), "+f"(c[3])
        : "r"(a0), "r"(a1), "r"(a2), "r"(a3), "r"(b0), "r"(b1));
}
__device__ __forceinline__ void mma_fp16(float c[4], uint32_t a0, uint32_t a1,
                                         uint32_t a2, uint32_t a3,
                                         uint32_t b0, uint32_t b1) {
    asm volatile(
        "mma.sync.aligned.m16n8k16.row.col.f32.f16.f16.f32 "
        "{%0,%1,%2,%3}, {%4,%5,%6,%7}, {%8,%9}, {%0,%1,%2,%3};\n"
        : "+f"(c[0]), "+f"(c[1]), "+f"(c[2]), "+f"(c[3])
        : "r"(a0), "r"(a1), "r"(a2), "r"(a3), "r"(b0), "r"(b1));
}
__device__ __forceinline__ void ldsm_x4(uint32_t& r0, uint32_t& r1,
                                        uint32_t& r2, uint32_t& r3,
                                        uint32_t addr) {
    asm volatile(
        "ldmatrix.sync.aligned.m8n8.x4.shared.b16 {%0,%1,%2,%3}, [%4];"
        : "=r"(r0), "=r"(r1), "=r"(r2), "=r"(r3) : "r"(addr));
}
__device__ __forceinline__ uint32_t smem_u32(const void* p) {
    uint32_t a;
    asm("{ .reg .u64 t; cvta.to.shared.u64 t, %1; cvt.u32.u64 %0, t; }"
        : "=r"(a) : "l"(p));
    return a;
}
__device__ __forceinline__ void cp16(uint32_t smem, const void* g) {
    asm volatile("cp.async.ca.shared.global [%0], [%1], 16;"
                 :: "r"(smem), "l"(g) : "memory");
}
#define CP_COMMIT() asm volatile("cp.async.commit_group;" ::: "memory")
#define CP_WAIT0() asm volatile("cp.async.wait_group 0;" ::: "memory")
#define CP_WAIT1() asm volatile("cp.async.wait_group 1;" ::: "memory")

// ---------------------------------------------------------------------------
// A-fragment reorder + tf32 round (round 9)
// ---------------------------------------------------------------------------
__global__ void afrag_kernel(const float* __restrict__ in,
                             float* __restrict__ out, int K) {
    int idx = blockIdx.x * 256 + threadIdx.x;
    int lane = idx & 31;
    int blk = idx >> 5;
    int KB = K >> 3;
    int cb = blk % KB, rb = blk / KB;
    int g = lane >> 2, tig = lane & 3;
    const float* p = in + (size_t)(rb * 16 + g) * K + cb * 8 + tig;
    float4 v;
    v.x = tf32f(p[0]);
    v.y = tf32f(p[(size_t)8 * K]);
    v.z = tf32f(p[4]);
    v.w = tf32f(p[(size_t)8 * K + 4]);
    ((float4*)out)[idx] = v;
}

// ---------------------------------------------------------------------------
// B-fragment reorder + tf32 round (round 9)
// ---------------------------------------------------------------------------
__global__ void bfrag_kernel(const float* __restrict__ in,
                             float* __restrict__ out, int N) {
    int idx = blockIdx.x * 256 + threadIdx.x;
    int lane = idx & 31;
    int blk = idx >> 5;
    int NB = N >> 3;
    int nb = blk % NB, kb = blk / NB;
    int g = lane >> 2, tig = lane & 3;
    const float* p = in + (size_t)(kb * 8 + tig) * N + nb * 8 + g;
    float2 v;
    v.x = tf32f(p[0]);
    v.y = tf32f(p[(size_t)4 * N]);
    ((float2*)out)[idx] = v;
}

// ---------------------------------------------------------------------------
// TF32 GEMM v3 (round 8/9, proven)
// ---------------------------------------------------------------------------
#define GEMM_SMEM_BYTES 65536

__global__ __launch_bounds__(256, 2)
void gemm_tf32_kernel(const float* __restrict__ Af, const float* __restrict__ Bf,
                      const float* __restrict__ bias, float* __restrict__ C,
                      int M, int N, int K) {
    extern __shared__ float sm[];
    const uint32_t smb = smem_u32(sm);
    const int tid = threadIdx.x;
    const int lane = tid & 31;
    const int warp = tid >> 5;
    const int wm = warp >> 2;
    const int wn = warp & 3;
    const int g = lane >> 2;
    const int tig = lane & 3;
    const int row0 = blockIdx.y * 128;
    const int col0 = blockIdx.x * 128;
    const int KB = K >> 3;
    const int NB = N >> 3;
    const int rb0 = row0 >> 4;
    const int nb0 = col0 >> 3;

    float acc[4][4][4];
#pragma unroll
    for (int im = 0; im < 4; im++)
#pragma unroll
        for (int in = 0; in < 4; in++)
#pragma unroll
            for (int r = 0; r < 4; r++) acc[im][in][r] = 0.0f;

    int a_rblk[4], a_kblk[4], a_l16[4];
    int b_kblk[4], b_nblk[4], b_w16[4];
#pragma unroll
    for (int s = 0; s < 4; s++) {
        int c = tid + s * 256;
        int ablk = c >> 5;
        a_rblk[s] = ablk >> 2;
        a_kblk[s] = ablk & 3;
        a_l16[s] = c & 31;
        int bblk = c >> 4;
        b_kblk[s] = bblk >> 4;
        b_nblk[s] = bblk & 15;
        b_w16[s] = c & 15;
    }

    const int nT = K / 32;

#pragma unroll
    for (int s = 0; s < 4; s++) {
        cp16(smb + (uint32_t)((a_rblk[s] * 4 + a_kblk[s]) * 512 + a_l16[s] * 16),
             Af + (((size_t)(rb0 + a_rblk[s]) * KB + a_kblk[s]) << 7) + a_l16[s] * 4);
        cp16(smb + 32768u + (uint32_t)((b_kblk[s] * 16 + b_nblk[s]) * 256 + b_w16[s] * 16),
             Bf + (((size_t)b_kblk[s] * NB + nb0 + b_nblk[s]) << 6) + b_w16[s] * 4);
    }
    CP_COMMIT();

    for (int t = 0; t < nT; t++) {
        if (t + 1 < nT) {
            const int kb = (t + 1) * 4;
            const uint32_t ao = ((t + 1) & 1) ? 16384u : 0u;
            const uint32_t bo = 32768u + (((t + 1) & 1) ? 16384u : 0u);
#pragma unroll
            for (int s = 0; s < 4; s++) {
                cp16(smb + ao + (uint32_t)((a_rblk[s] * 4 + a_kblk[s]) * 512 + a_l16[s] * 16),
                     Af + (((size_t)(rb0 + a_rblk[s]) * KB + kb + a_kblk[s]) << 7) + a_l16[s] * 4);
                cp16(smb + bo + (uint32_t)((b_kblk[s] * 16 + b_nblk[s]) * 256 + b_w16[s] * 16),
                     Bf + (((size_t)(kb + b_kblk[s]) * NB + nb0 + b_nblk[s]) << 6) + b_w16[s] * 4);
            }
            CP_COMMIT();
            CP_WAIT1();
        } else {
            CP_WAIT0();
        }
        __syncthreads();

        const float* As = sm + (t & 1) * 4096;
        const float* Bs = sm + 8192 + (t & 1) * 4096;

#pragma unroll
        for (int kk = 0; kk < 4; kk++) {
            float4 af[4];
#pragma unroll
            for (int im = 0; im < 4; im++)
                af[im] = *(const float4*)(As + ((wm * 4 + im) * 4 + kk) * 128 + lane * 4);
            float2 bf[4];
#pragma unroll
            for (int in = 0; in < 4; in++)
                bf[in] = *(const float2*)(Bs + (kk * 16 + wn * 4 + in) * 64 + lane * 2);
#pragma unroll
            for (int im = 0; im < 4; im++)
#pragma unroll
                for (int in = 0; in < 4; in++)
                    mma_tf32(acc[im][in],
                             __float_as_uint(af[im].x), __float_as_uint(af[im].y),
                             __float_as_uint(af[im].z), __float_as_uint(af[im].w),
                             __float_as_uint(bf[in].x), __float_as_uint(bf[in].y));
        }
        __syncthreads();
    }

#pragma unroll
    for (int im = 0; im < 4; im++) {
        int r = row0 + wm * 64 + im * 16 + g;
#pragma unroll
        for (int in = 0; in < 4; in++) {
            int c = col0 + wn * 32 + in * 8 + tig * 2;
            float b0 = bias[c], b1 = bias[c + 1];
            float2 v0 = make_float2(acc[im][in][0] + b0, acc[im][in][1] + b1);
            float2 v1 = make_float2(acc[im][in][2] + b0, acc[im][in][3] + b1);
            *(float2*)&C[(size_t)r * N + c] = v0;
            *(float2*)&C[(size_t)(r + 8) * N + c] = v1;
        }
    }
}

// ---------------------------------------------------------------------------
// RoPE + scatter: q/k bf16 hi/lo, v single fp16 transposed [bh][d][t]
// ---------------------------------------------------------------------------
__global__ __launch_bounds__(256)
void rope_scatter_split_kernel(const float* __restrict__ qkv,
                               const float2* __restrict__ rope,
                               __nv_bfloat16* __restrict__ qh,
                               __nv_bfloat16* __restrict__ ql,
                               __nv_bfloat16* __restrict__ kh,
                               __nv_bfloat16* __restrict__ kl,
                               __half* __restrict__ vt) {
    __shared__ __half vsh[64][66];

    int bh = blockIdx.y;
    int tb = blockIdx.x * 64;
    int b = bh >> 4;
    int h = bh & 15;
    int tid = threadIdx.x;

    const float SCL = 0.125f * 1.4426950408889634f;

#pragma unroll
    for (int e = 0; e < 16; e++) {
        int idx = tid + e * 256;
        int tl = idx >> 6;
        int d = idx & 63;
        int t = tb + tl;
        size_t base = (size_t)(b * TSEQ + t) * QKVCOLS + h * DHEAD;
        float2 cs = rope[t * 32 + (d & 31)];

        float qv = qkv[base + d];
        float kv = qkv[base + CDIM + d];
        float vv = qkv[base + 2 * CDIM + d];
        int dp = (d < 32) ? d + 32 : d - 32;
        float sgn = (d < 32) ? -1.0f : 1.0f;
        float qr = qkv[base + dp];
        float kr = qkv[base + CDIM + dp];

        float qrot = (qv * cs.x + sgn * qr * cs.y) * SCL;
        float krot = kv * cs.x + sgn * kr * cs.y;

        size_t o = ((size_t)bh * TSEQ + t) * DHEAD + d;
        __nv_bfloat16 qhv = __float2bfloat16(qrot);
        __nv_bfloat16 khv = __float2bfloat16(krot);
        qh[o] = qhv;
        ql[o] = __float2bfloat16(qrot - __bfloat162float(qhv));
        kh[o] = khv;
        kl[o] = __float2bfloat16(krot - __bfloat162float(khv));

        vsh[d][tl] = __float2half_rn(vv);
    }
    __syncthreads();
#pragma unroll
    for (int e = 0; e < 16; e++) {
        int idx = tid + e * 256;
        int d = idx >> 6;
        int tl = idx & 63;
        vt[((size_t)bh * DHEAD + d) * TSEQ + tb + tl] = vsh[d][tl];
    }
}

// ---------------------------------------------------------------------------
// Flash attention v7: S = bf16-split (3 mma, ldmatrix), PV = single fp16
// (1 ldmatrix + 2 mma per dbp). Per-iter warp mma: 96 + 32 = 128.
// ---------------------------------------------------------------------------
#define FRS 144
#define OFF_KH 0
#define OFF_KL 9216
#define OFF_VT 18432
#define BUFB 27648
#define FLASH_SMEM_BYTES (2 * BUFB)   // 55296

#define NEGBIG (-1e30f)

__global__ __launch_bounds__(128, 3)
void flash_mma_kernel(const __nv_bfloat16* __restrict__ QH,
                      const __nv_bfloat16* __restrict__ QL,
                      const __nv_bfloat16* __restrict__ KH,
                      const __nv_bfloat16* __restrict__ KL,
                      const __half* __restrict__ VT) {
    extern __shared__ char smc[];
    const uint32_t smb = smem_u32(smc);

    int bh = blockIdx.y;
    int qt = gridDim.x - 1 - blockIdx.x;
    int q0 = qt * 64;

    int tid = threadIdx.x;
    int lane = tid & 31;
    int w = tid >> 5;
    int g = lane >> 2;
    int tig = lane & 3;
    const int r0 = w * 16 + g;

    const int jj = lane & 7;
    const uint32_t ldsm_base =
        (uint32_t)((jj + ((lane >> 4) & 1) * 8) * FRS + ((lane >> 3) & 1) * 16);

    const __nv_bfloat16* KHg = KH + (size_t)bh * TSEQ * DHEAD;
    const __nv_bfloat16* KLg = KL + (size_t)bh * TSEQ * DHEAD;
    const __half* VTg = VT + (size_t)bh * DHEAD * TSEQ;

    {
#pragma unroll
        for (int s = 0; s < 4; s++) {
            int f = tid + s * 128;
            int r = f >> 3;
            int c = (f & 7) * 8;
            uint32_t ro = (uint32_t)(r * FRS + c * 2);
            cp16(smb + OFF_KH + ro, KHg + (size_t)r * DHEAD + c);
            cp16(smb + OFF_KL + ro, KLg + (size_t)r * DHEAD + c);
            cp16(smb + OFF_VT + ro, VTg + (size_t)r * TSEQ + c);
        }
        CP_COMMIT();
    }

    uint32_t qah[4][4], qal[4][4];
    {
        const __nv_bfloat16* Qhg = QH + ((size_t)bh * TSEQ + q0 + r0) * DHEAD;
        const __nv_bfloat16* Qlg = QL + ((size_t)bh * TSEQ + q0 + r0) * DHEAD;
#pragma unroll
        for (int ks = 0; ks < 4; ks++) {
            int c0 = ks * 16 + 2 * tig;
            qah[ks][0] = *(const uint32_t*)(Qhg + c0);
            qah[ks][1] = *(const uint32_t*)(Qhg + 8 * DHEAD + c0);
            qah[ks][2] = *(const uint32_t*)(Qhg + c0 + 8);
            qah[ks][3] = *(const uint32_t*)(Qhg + 8 * DHEAD + c0 + 8);
            qal[ks][0] = *(const uint32_t*)(Qlg + c0);
            qal[ks][1] = *(const uint32_t*)(Qlg + 8 * DHEAD + c0);
            qal[ks][2] = *(const uint32_t*)(Qlg + c0 + 8);
            qal[ks][3] = *(const uint32_t*)(Qlg + 8 * DHEAD + c0 + 8);
        }
    }

    float oacc[8][4];
#pragma unroll
    for (int db = 0; db < 8; db++)
#pragma unroll
        for (int r = 0; r < 4; r++) oacc[db][r] = 0.0f;
    float m0 = NEGBIG, m1 = NEGBIG, l0 = 0.0f, l1 = 0.0f;

    for (int jt = 0; jt <= qt; jt++) {
        CP_WAIT0();
        __syncthreads();

        if (jt < qt) {
            int k0n = (jt + 1) * 64;
            uint32_t nb_ = smb + ((jt + 1) & 1) * BUFB;
#pragma unroll
            for (int s = 0; s < 4; s++) {
                int f = tid + s * 128;
                int r = f >> 3;
                int c = (f & 7) * 8;
                uint32_t ro = (uint32_t)(r * FRS + c * 2);
                cp16(nb_ + OFF_KH + ro, KHg + (size_t)(k0n + r) * DHEAD + c);
                cp16(nb_ + OFF_KL + ro, KLg + (size_t)(k0n + r) * DHEAD + c);
                cp16(nb_ + OFF_VT + ro, VTg + (size_t)r * TSEQ + k0n + c);
            }
            CP_COMMIT();
        }

        const uint32_t bufa = smb + (jt & 1) * BUFB + ldsm_base;

        // ---- S = Q K^T (bf16 split, ldmatrix) ----
        float sacc[8][4];
#pragma unroll
        for (int nb = 0; nb < 8; nb++)
#pragma unroll
            for (int r = 0; r < 4; r++) sacc[nb][r] = 0.0f;

#pragma unroll
        for (int ks = 0; ks < 4; ks++) {
            const uint32_t ko = (uint32_t)(ks * 32);
#pragma unroll
            for (int nbp = 0; nbp < 4; nbp++) {
                const uint32_t ba = bufa + (uint32_t)(nbp * 16 * FRS) + ko;
                uint32_t h0, h1, h2, h3, e0, e1, e2, e3;
                ldsm_x4(h0, h1, h2, h3, ba + OFF_KH);
                ldsm_x4(e0, e1, e2, e3, ba + OFF_KL);
                mma_bf16(sacc[2 * nbp], qah[ks][0], qah[ks][1], qah[ks][2], qah[ks][3], h0, h1);
                mma_bf16(sacc[2 * nbp], qah[ks][0], qah[ks][1], qah[ks][2], qah[ks][3], e0, e1);
                mma_bf16(sacc[2 * nbp], qal[ks][0], qal[ks][1], qal[ks][2], qal[ks][3], h0, h1);
                mma_bf16(sacc[2 * nbp + 1], qah[ks][0], qah[ks][1], qah[ks][2], qah[ks][3], h2, h3);
                mma_bf16(sacc[2 * nbp + 1], qah[ks][0], qah[ks][1], qah[ks][2], qah[ks][3], e2, e3);
                mma_bf16(sacc[2 * nbp + 1], qal[ks][0], qal[ks][1], qal[ks][2], qal[ks][3], h2, h3);
            }
        }

        if (jt == qt) {
#pragma unroll
            for (int nb = 0; nb < 8; nb++) {
                int c0 = nb * 8 + 2 * tig;
#pragma unroll
                for (int e = 0; e < 2; e++) {
                    if (c0 + e > r0) sacc[nb][e] = NEGBIG;
                    if (c0 + e > r0 + 8) sacc[nb][2 + e] = NEGBIG;
                }
            }
        }

        // ---- online softmax (log2 domain) ----
        float tm0 = NEGBIG, tm1 = NEGBIG;
#pragma unroll
        for (int nb = 0; nb < 8; nb++) {
            tm0 = fmaxf(tm0, fmaxf(sacc[nb][0], sacc[nb][1]));
            tm1 = fmaxf(tm1, fmaxf(sacc[nb][2], sacc[nb][3]));
        }
        tm0 = fmaxf(tm0, __shfl_xor_sync(0xffffffffu, tm0, 1));
        tm0 = fmaxf(tm0, __shfl_xor_sync(0xffffffffu, tm0, 2));
        tm1 = fmaxf(tm1, __shfl_xor_sync(0xffffffffu, tm1, 1));
        tm1 = fmaxf(tm1, __shfl_xor_sync(0xffffffffu, tm1, 2));

        float mn0 = fmaxf(m0, tm0);
        float mn1 = fmaxf(m1, tm1);
        float corr0 = ex2f(m0 - mn0);
        float corr1 = ex2f(m1 - mn1);
        float rs0 = 0.0f, rs1 = 0.0f;
#pragma unroll
        for (int nb = 0; nb < 8; nb++) {
            sacc[nb][0] = ex2f(sacc[nb][0] - mn0);
            sacc[nb][1] = ex2f(sacc[nb][1] - mn0);
            sacc[nb][2] = ex2f(sacc[nb][2] - mn1);
            sacc[nb][3] = ex2f(sacc[nb][3] - mn1);
            rs0 += sacc[nb][0] + sacc[nb][1];
            rs1 += sacc[nb][2] + sacc[nb][3];
        }
        rs0 += __shfl_xor_sync(0xffffffffu, rs0, 1);
        rs0 += __shfl_xor_sync(0xffffffffu, rs0, 2);
        rs1 += __shfl_xor_sync(0xffffffffu, rs1, 1);
        rs1 += __shfl_xor_sync(0xffffffffu, rs1, 2);

        l0 = l0 * corr0 + rs0;
        l1 = l1 * corr1 + rs1;
        m0 = mn0;
        m1 = mn1;
#pragma unroll
        for (int db = 0; db < 8; db++) {
            oacc[db][0] *= corr0;
            oacc[db][1] *= corr0;
            oacc[db][2] *= corr1;
            oacc[db][3] *= corr1;
        }

        // ---- O += P @ V : single fp16 (P from S accumulators) ----
#pragma unroll
        for (int ks = 0; ks < 4; ks++) {
            uint32_t p16[4];
            p16[0] = h2u(__floats2half2_rn(sacc[2 * ks][0], sacc[2 * ks][1]));
            p16[1] = h2u(__floats2half2_rn(sacc[2 * ks][2], sacc[2 * ks][3]));
            p16[2] = h2u(__floats2half2_rn(sacc[2 * ks + 1][0], sacc[2 * ks + 1][1]));
            p16[3] = h2u(__floats2half2_rn(sacc[2 * ks + 1][2], sacc[2 * ks + 1][3]));
            const uint32_t ko = (uint32_t)(ks * 32);
#pragma unroll
            for (int dbp = 0; dbp < 4; dbp++) {
                const uint32_t ba = bufa + (uint32_t)(dbp * 16 * FRS) + ko;
                uint32_t h0, h1, h2, h3;
                ldsm_x4(h0, h1, h2, h3, ba + OFF_VT);
                mma_fp16(oacc[2 * dbp], p16[0], p16[1], p16[2], p16[3], h0, h1);
                mma_fp16(oacc[2 * dbp + 1], p16[0], p16[1], p16[2], p16[3], h2, h3);
            }
        }
    }

    float inv0 = 1.0f / l0;
    float inv1 = 1.0f / l1;
    int b = bh >> 4;
    int h = bh & 15;
    int t0 = q0 + r0;
    int t1 = t0 + 8;
#pragma unroll
    for (int db = 0; db < 8; db++) {
        int col = h * 64 + db * 8 + 2 * tig;
        float2 y0 = make_float2(oacc[db][0] * inv0, oacc[db][1] * inv0);
        float2 y1 = make_float2(oacc[db][2] * inv1, oacc[db][3] * inv1);
        *(float2*)&g_y[(size_t)(b * TSEQ + t0) * CDIM + col] = y0;
        *(float2*)&g_y[(size_t)(b * TSEQ + t1) * CDIM + col] = y1;
    }
}

// ---------------------------------------------------------------------------
// Launch
// ---------------------------------------------------------------------------
extern "C" void kernel_launch(void* const* d_in, const int* in_sizes, int n_in,
                              void* d_out, int out_size) {
    const float* x      = (const float*)d_in[0];
    const float* w_attn = (const float*)d_in[1];
    const float* b_attn = (const float*)d_in[2];
    const float* w_proj = (const float*)d_in[3];
    const float* b_proj = (const float*)d_in[4];
    float* out = (float*)d_out;

    float *qkv, *y, *xf, *waf, *wpf, *yf;
    float2* rope;
    __nv_bfloat16 *qh, *ql, *kh, *kl;
    __half* vt;
    cudaGetSymbolAddress((void**)&qkv, g_qkv);
    cudaGetSymbolAddress((void**)&xf, g_xf);
    cudaGetSymbolAddress((void**)&waf, g_waf);
    cudaGetSymbolAddress((void**)&wpf, g_wpf);
    cudaGetSymbolAddress((void**)&yf, g_yf);
    cudaGetSymbolAddress((void**)&qh, g_qh);
    cudaGetSymbolAddress((void**)&ql, g_ql);
    cudaGetSymbolAddress((void**)&kh, g_kh);
    cudaGetSymbolAddress((void**)&kl, g_kl);
    cudaGetSymbolAddress((void**)&vt, g_vt);
    cudaGetSymbolAddress((void**)&y, g_y);
    cudaGetSymbolAddress((void**)&rope, g_rope);

    cudaFuncSetAttribute(gemm_tf32_kernel,
                         cudaFuncAttributeMaxDynamicSharedMemorySize,
                         GEMM_SMEM_BYTES);
    cudaFuncSetAttribute(flash_mma_kernel,
                         cudaFuncAttributeMaxDynamicSharedMemorySize,
                         FLASH_SMEM_BYTES);

    build_rope_kernel<<<(TSEQ * 32 + 255) / 256, 256>>>(rope);

    afrag_kernel<<<(MROWS / 16) * (CDIM / 8) * 32 / 256, 256>>>(x, xf, CDIM);
    bfrag_kernel<<<(CDIM / 8) * (QKVCOLS / 8) * 32 / 256, 256>>>(w_attn, waf, QKVCOLS);
    bfrag_kernel<<<(CDIM / 8) * (CDIM / 8) * 32 / 256, 256>>>(w_proj, wpf, CDIM);

    gemm_tf32_kernel<<<dim3(QKVCOLS / 128, MROWS / 128), 256, GEMM_SMEM_BYTES>>>(
        xf, waf, b_attn, qkv, MROWS, QKVCOLS, CDIM);

    rope_scatter_split_kernel<<<dim3(TSEQ / 64, BSZ * NHEAD), 256>>>(
        qkv, rope, qh, ql, kh, kl, vt);

    flash_mma_kernel<<<dim3(TSEQ / 64, BSZ * NHEAD), 128, FLASH_SMEM_BYTES>>>(
        qh, ql, kh, kl, vt);

    afrag_kernel<<<(MROWS / 16) * (CDIM / 8) * 32 / 256, 256>>>(y, yf, CDIM);
    gemm_tf32_kernel<<<dim3(CDIM / 128, MROWS / 128), 256, GEMM_SMEM_BYTES>>>(
        yf, wpf, b_proj, out, MROWS, CDIM, CDIM);
}

// round 13
// speedup vs baseline: 1.5936x; 1.1582x over previous
#include <cuda_runtime.h>
#include <cuda_fp16.h>
#include <math.h>
#include <math_constants.h>
#include <stdint.h>

// Problem constants
#define BSZ 2
#define TSEQ 2048
#define CDIM 1024
#define NHEAD 16
#define DHEAD 64
#define MROWS (BSZ * TSEQ)          // 4096
#define QKVCOLS (3 * CDIM)          // 3072

// ---------------------------------------------------------------------------
// Scratch
// ---------------------------------------------------------------------------
__device__ float g_qkv[(size_t)MROWS * QKVCOLS];
__device__ float g_xf[(size_t)MROWS * CDIM];          // x, A-frag order, tf32
__device__ float g_waf[(size_t)CDIM * QKVCOLS];       // w_attn, B-frag order, tf32
__device__ float g_wpf[(size_t)CDIM * CDIM];          // w_proj, B-frag order, tf32
__device__ float g_yf[(size_t)MROWS * CDIM];          // y, A-frag order, tf32
__device__ __half g_qf[(size_t)BSZ * NHEAD * TSEQ * DHEAD];   // scaled, fp16
__device__ __half g_kf[(size_t)BSZ * NHEAD * TSEQ * DHEAD];   // fp16
__device__ __half g_vt[(size_t)BSZ * NHEAD * DHEAD * TSEQ];   // [bh][d][t], fp16
__device__ float g_y[(size_t)MROWS * CDIM];
__device__ float2 g_rope[TSEQ * (DHEAD / 2)];

// ---------------------------------------------------------------------------
// RoPE table
// ---------------------------------------------------------------------------
__global__ void build_rope_kernel(float2* __restrict__ table) {
    int i = blockIdx.x * blockDim.x + threadIdx.x;
    if (i >= TSEQ * 32) return;
    int t = i >> 5;
    int j = i & 31;
    double inv = pow(10000.0, -(double)j / 32.0);
    double ang = (double)t * inv;
    table[i] = make_float2((float)cos(ang), (float)sin(ang));
}

// ---------------------------------------------------------------------------
// Math helpers
// ---------------------------------------------------------------------------
__device__ __forceinline__ uint32_t f2tf32(float x) {
    uint32_t r;
    asm("cvt.rna.tf32.f32 %0, %1;" : "=r"(r) : "f"(x));
    return r;
}
__device__ __forceinline__ float tf32f(float x) {
    return __uint_as_float(f2tf32(x));
}
__device__ __forceinline__ float ex2f(float x) {
    float r;
    asm("ex2.approx.ftz.f32 %0, %1;" : "=f"(r) : "f"(x));
    return r;
}
__device__ __forceinline__ uint32_t h2u(__half2 h) {
    return *reinterpret_cast<uint32_t*>(&h);
}
__device__ __forceinline__ void mma_tf32(float c[4], uint32_t a0, uint32_t a1,
                                         uint32_t a2, uint32_t a3,
                                         uint32_t b0, uint32_t b1) {
    asm volatile(
        "mma.sync.aligned.m16n8k8.row.col.f32.tf32.tf32.f32 "
        "{%0,%1,%2,%3}, {%4,%5,%6,%7}, {%8,%9}, {%0,%1,%2,%3};\n"
        : "+f"(c[0]), "+f"(c[1]), "+f"(c[2]), "+f"(c[3])
        : "r"(a0), "r"(a1), "r"(a2), "r"(a3), "r"(b0), "r"(b1));
}
__device__ __forceinline__ void mma_fp16(float c[4], uint32_t a0, uint32_t a1,
                                         uint32_t a2, uint32_t a3,
                                         uint32_t b0, uint32_t b1) {
    asm volatile(
        "mma.sync.aligned.m16n8k16.row.col.f32.f16.f16.f32 "
        "{%0,%1,%2,%3}, {%4,%5,%6,%7}, {%8,%9}, {%0,%1,%2,%3};\n"
        : "+f"(c[0]), "+f"(c[1]), "+f"(c[2]), "+f"(c[3])
        : "r"(a0), "r"(a1), "r"(a2), "r"(a3), "r"(b0), "r"(b1));
}
__device__ __forceinline__ void ldsm_x4(uint32_t& r0, uint32_t& r1,
                                        uint32_t& r2, uint32_t& r3,
                                        uint32_t addr) {
    asm volatile(
        "ldmatrix.sync.aligned.m8n8.x4.shared.b16 {%0,%1,%2,%3}, [%4];"
        : "=r"(r0), "=r"(r1), "=r"(r2), "=r"(r3) : "r"(addr));
}
__device__ __forceinline__ uint32_t smem_u32(const void* p) {
    uint32_t a;
    asm("{ .reg .u64 t; cvta.to.shared.u64 t, %1; cvt.u32.u64 %0, t; }"
        : "=r"(a) : "l"(p));
    return a;
}
__device__ __forceinline__ void cp16(uint32_t smem, const void* g) {
    asm volatile("cp.async.ca.shared.global [%0], [%1], 16;"
                 :: "r"(smem), "l"(g) : "memory");
}
#define CP_COMMIT() asm volatile("cp.async.commit_group;" ::: "memory")
#define CP_WAIT0() asm volatile("cp.async.wait_group 0;" ::: "memory")
#define CP_WAIT1() asm volatile("cp.async.wait_group 1;" ::: "memory")

// ---------------------------------------------------------------------------
// A-fragment reorder + tf32 round
// ---------------------------------------------------------------------------
__global__ void afrag_kernel(const float* __restrict__ in,
                             float* __restrict__ out, int K) {
    int idx = blockIdx.x * 256 + threadIdx.x;
    int lane = idx & 31;
    int blk = idx >> 5;
    int KB = K >> 3;
    int cb = blk % KB, rb = blk / KB;
    int g = lane >> 2, tig = lane & 3;
    const float* p = in + (size_t)(rb * 16 + g) * K + cb * 8 + tig;
    float4 v;
    v.x = tf32f(p[0]);
    v.y = tf32f(p[(size_t)8 * K]);
    v.z = tf32f(p[4]);
    v.w = tf32f(p[(size_t)8 * K + 4]);
    ((float4*)out)[idx] = v;
}

// ---------------------------------------------------------------------------
// B-fragment reorder + tf32 round
// ---------------------------------------------------------------------------
__global__ void bfrag_kernel(const float* __restrict__ in,
                             float* __restrict__ out, int N) {
    int idx = blockIdx.x * 256 + threadIdx.x;
    int lane = idx & 31;
    int blk = idx >> 5;
    int NB = N >> 3;
    int nb = blk % NB, kb = blk / NB;
    int g = lane >> 2, tig = lane & 3;
    const float* p = in + (size_t)(kb * 8 + tig) * N + nb * 8 + g;
    float2 v;
    v.x = tf32f(p[0]);
    v.y = tf32f(p[(size_t)4 * N]);
    ((float2*)out)[idx] = v;
}

// ---------------------------------------------------------------------------
// TF32 GEMM v3 (proven)
// ---------------------------------------------------------------------------
#define GEMM_SMEM_BYTES 65536

__global__ __launch_bounds__(256, 2)
void gemm_tf32_kernel(const float* __restrict__ Af, const float* __restrict__ Bf,
                      const float* __restrict__ bias, float* __restrict__ C,
                      int M, int N, int K) {
    extern __shared__ float sm[];
    const uint32_t smb = smem_u32(sm);
    const int tid = threadIdx.x;
    const int lane = tid & 31;
    const int warp = tid >> 5;
    const int wm = warp >> 2;
    const int wn = warp & 3;
    const int g = lane >> 2;
    const int tig = lane & 3;
    const int row0 = blockIdx.y * 128;
    const int col0 = blockIdx.x * 128;
    const int KB = K >> 3;
    const int NB = N >> 3;
    const int rb0 = row0 >> 4;
    const int nb0 = col0 >> 3;

    float acc[4][4][4];
#pragma unroll
    for (int im = 0; im < 4; im++)
#pragma unroll
        for (int in = 0; in < 4; in++)
#pragma unroll
            for (int r = 0; r < 4; r++) acc[im][in][r] = 0.0f;

    int a_rblk[4], a_kblk[4], a_l16[4];
    int b_kblk[4], b_nblk[4], b_w16[4];
#pragma unroll
    for (int s = 0; s < 4; s++) {
        int c = tid + s * 256;
        int ablk = c >> 5;
        a_rblk[s] = ablk >> 2;
        a_kblk[s] = ablk & 3;
        a_l16[s] = c & 31;
        int bblk = c >> 4;
        b_kblk[s] = bblk >> 4;
        b_nblk[s] = bblk & 15;
        b_w16[s] = c & 15;
    }

    const int nT = K / 32;

#pragma unroll
    for (int s = 0; s < 4; s++) {
        cp16(smb + (uint32_t)((a_rblk[s] * 4 + a_kblk[s]) * 512 + a_l16[s] * 16),
             Af + (((size_t)(rb0 + a_rblk[s]) * KB + a_kblk[s]) << 7) + a_l16[s] * 4);
        cp16(smb + 32768u + (uint32_t)((b_kblk[s] * 16 + b_nblk[s]) * 256 + b_w16[s] * 16),
             Bf + (((size_t)b_kblk[s] * NB + nb0 + b_nblk[s]) << 6) + b_w16[s] * 4);
    }
    CP_COMMIT();

    for (int t = 0; t < nT; t++) {
        if (t + 1 < nT) {
            const int kb = (t + 1) * 4;
            const uint32_t ao = ((t + 1) & 1) ? 16384u : 0u;
            const uint32_t bo = 32768u + (((t + 1) & 1) ? 16384u : 0u);
#pragma unroll
            for (int s = 0; s < 4; s++) {
                cp16(smb + ao + (uint32_t)((a_rblk[s] * 4 + a_kblk[s]) * 512 + a_l16[s] * 16),
                     Af + (((size_t)(rb0 + a_rblk[s]) * KB + kb + a_kblk[s]) << 7) + a_l16[s] * 4);
                cp16(smb + bo + (uint32_t)((b_kblk[s] * 16 + b_nblk[s]) * 256 + b_w16[s] * 16),
                     Bf + (((size_t)(kb + b_kblk[s]) * NB + nb0 + b_nblk[s]) << 6) + b_w16[s] * 4);
            }
            CP_COMMIT();
            CP_WAIT1();
        } else {
            CP_WAIT0();
        }
        __syncthreads();

        const float* As = sm + (t & 1) * 4096;
        const float* Bs = sm + 8192 + (t & 1) * 4096;

#pragma unroll
        for (int kk = 0; kk < 4; kk++) {
            float4 af[4];
#pragma unroll
            for (int im = 0; im < 4; im++)
                af[im] = *(const float4*)(As + ((wm * 4 + im) * 4 + kk) * 128 + lane * 4);
            float2 bf[4];
#pragma unroll
            for (int in = 0; in < 4; in++)
                bf[in] = *(const float2*)(Bs + (kk * 16 + wn * 4 + in) * 64 + lane * 2);
#pragma unroll
            for (int im = 0; im < 4; im++)
#pragma unroll
                for (int in = 0; in < 4; in++)
                    mma_tf32(acc[im][in],
                             __float_as_uint(af[im].x), __float_as_uint(af[im].y),
                             __float_as_uint(af[im].z), __float_as_uint(af[im].w),
                             __float_as_uint(bf[in].x), __float_as_uint(bf[in].y));
        }
        __syncthreads();
    }

#pragma unroll
    for (int im = 0; im < 4; im++) {
        int r = row0 + wm * 64 + im * 16 + g;
#pragma unroll
        for (int in = 0; in < 4; in++) {
            int c = col0 + wn * 32 + in * 8 + tig * 2;
            float b0 = bias[c], b1 = bias[c + 1];
            float2 v0 = make_float2(acc[im][in][0] + b0, acc[im][in][1] + b1);
            float2 v1 = make_float2(acc[im][in][2] + b0, acc[im][in][3] + b1);
            *(float2*)&C[(size_t)r * N + c] = v0;
            *(float2*)&C[(size_t)(r + 8) * N + c] = v1;
        }
    }
}

// ---------------------------------------------------------------------------
// RoPE + scatter: q (scaled) / k fp16 [bh][t][d], v fp16 transposed [bh][d][t]
// ---------------------------------------------------------------------------
__global__ __launch_bounds__(256)
void rope_scatter_kernel(const float* __restrict__ qkv,
                         const float2* __restrict__ rope,
                         __half* __restrict__ qf, __half* __restrict__ kf,
                         __half* __restrict__ vt) {
    __shared__ __half vsh[64][66];

    int bh = blockIdx.y;
    int tb = blockIdx.x * 64;
    int b = bh >> 4;
    int h = bh & 15;
    int tid = threadIdx.x;

    const float SCL = 0.125f * 1.4426950408889634f;

#pragma unroll
    for (int e = 0; e < 16; e++) {
        int idx = tid + e * 256;
        int tl = idx >> 6;
        int d = idx & 63;
        int t = tb + tl;
        size_t base = (size_t)(b * TSEQ + t) * QKVCOLS + h * DHEAD;
        float2 cs = rope[t * 32 + (d & 31)];

        float qv = qkv[base + d];
        float kv = qkv[base + CDIM + d];
        float vv = qkv[base + 2 * CDIM + d];
        int dp = (d < 32) ? d + 32 : d - 32;
        float sgn = (d < 32) ? -1.0f : 1.0f;
        float qr = qkv[base + dp];
        float kr = qkv[base + CDIM + dp];

        float qrot = (qv * cs.x + sgn * qr * cs.y) * SCL;
        float krot = kv * cs.x + sgn * kr * cs.y;

        size_t o = ((size_t)bh * TSEQ + t) * DHEAD + d;
        qf[o] = __float2half_rn(qrot);
        kf[o] = __float2half_rn(krot);
        vsh[d][tl] = __float2half_rn(vv);
    }
    __syncthreads();
#pragma unroll
    for (int e = 0; e < 16; e++) {
        int idx = tid + e * 256;
        int d = idx >> 6;
        int tl = idx & 63;
        vt[((size_t)bh * DHEAD + d) * TSEQ + tb + tl] = vsh[d][tl];
    }
}

// ---------------------------------------------------------------------------
// Flash attention v8: S single fp16 mma, PV single fp16 mma.
// Per-iter warp mma: 32 + 32 = 64.  Buffers: K fp16 + V^T fp16 = 18 KB.
// ---------------------------------------------------------------------------
#define FRS 144
#define OFF_K 0
#define OFF_VT 9216
#define BUFB 18432
#define FLASH_SMEM_BYTES (2 * BUFB)   // 36864

#define NEGBIG (-1e30f)

__global__ __launch_bounds__(128, 3)
void flash_mma_kernel(const __half* __restrict__ QF,
                      const __half* __restrict__ KF,
                      const __half* __restrict__ VT) {
    extern __shared__ char smc[];
    const uint32_t smb = smem_u32(smc);

    int bh = blockIdx.y;
    int qt = gridDim.x - 1 - blockIdx.x;
    int q0 = qt * 64;

    int tid = threadIdx.x;
    int lane = tid & 31;
    int w = tid >> 5;
    int g = lane >> 2;
    int tig = lane & 3;
    const int r0 = w * 16 + g;

    const int jj = lane & 7;
    const uint32_t ldsm_base =
        (uint32_t)((jj + ((lane >> 4) & 1) * 8) * FRS + ((lane >> 3) & 1) * 16);

    const __half* KFg = KF + (size_t)bh * TSEQ * DHEAD;
    const __half* VTg = VT + (size_t)bh * DHEAD * TSEQ;

    {
#pragma unroll
        for (int s = 0; s < 4; s++) {
            int f = tid + s * 128;
            int r = f >> 3;
            int c = (f & 7) * 8;
            uint32_t ro = (uint32_t)(r * FRS + c * 2);
            cp16(smb + OFF_K + ro, KFg + (size_t)r * DHEAD + c);
            cp16(smb + OFF_VT + ro, VTg + (size_t)r * TSEQ + c);
        }
        CP_COMMIT();
    }

    // ---- Q fragments in registers (fp16) ----
    uint32_t qa[4][4];
    {
        const __half* Qg = QF + ((size_t)bh * TSEQ + q0 + r0) * DHEAD;
#pragma unroll
        for (int ks = 0; ks < 4; ks++) {
            int c0 = ks * 16 + 2 * tig;
            qa[ks][0] = *(const uint32_t*)(Qg + c0);
            qa[ks][1] = *(const uint32_t*)(Qg + 8 * DHEAD + c0);
            qa[ks][2] = *(const uint32_t*)(Qg + c0 + 8);
            qa[ks][3] = *(const uint32_t*)(Qg + 8 * DHEAD + c0 + 8);
        }
    }

    float oacc[8][4];
#pragma unroll
    for (int db = 0; db < 8; db++)
#pragma unroll
        for (int r = 0; r < 4; r++) oacc[db][r] = 0.0f;
    float m0 = NEGBIG, m1 = NEGBIG, l0 = 0.0f, l1 = 0.0f;

    for (int jt = 0; jt <= qt; jt++) {
        CP_WAIT0();
        __syncthreads();

        if (jt < qt) {
            int k0n = (jt + 1) * 64;
            uint32_t nb_ = smb + ((jt + 1) & 1) * BUFB;
#pragma unroll
            for (int s = 0; s < 4; s++) {
                int f = tid + s * 128;
                int r = f >> 3;
                int c = (f & 7) * 8;
                uint32_t ro = (uint32_t)(r * FRS + c * 2);
                cp16(nb_ + OFF_K + ro, KFg + (size_t)(k0n + r) * DHEAD + c);
                cp16(nb_ + OFF_VT + ro, VTg + (size_t)r * TSEQ + k0n + c);
            }
            CP_COMMIT();
        }

        const uint32_t bufa = smb + (jt & 1) * BUFB + ldsm_base;

        // ---- S = Q K^T (single fp16 mma per (ks, n-pair)) ----
        float sacc[8][4];
#pragma unroll
        for (int nb = 0; nb < 8; nb++)
#pragma unroll
            for (int r = 0; r < 4; r++) sacc[nb][r] = 0.0f;

#pragma unroll
        for (int ks = 0; ks < 4; ks++) {
            const uint32_t ko = (uint32_t)(ks * 32);
#pragma unroll
            for (int nbp = 0; nbp < 4; nbp++) {
                const uint32_t ba = bufa + (uint32_t)(nbp * 16 * FRS) + ko;
                uint32_t b0, b1, b2, b3;
                ldsm_x4(b0, b1, b2, b3, ba + OFF_K);
                mma_fp16(sacc[2 * nbp], qa[ks][0], qa[ks][1], qa[ks][2], qa[ks][3], b0, b1);
                mma_fp16(sacc[2 * nbp + 1], qa[ks][0], qa[ks][1], qa[ks][2], qa[ks][3], b2, b3);
            }
        }

        // ---- causal mask (diagonal tile only) ----
        if (jt == qt) {
#pragma unroll
            for (int nb = 0; nb < 8; nb++) {
                int c0 = nb * 8 + 2 * tig;
#pragma unroll
                for (int e = 0; e < 2; e++) {
                    if (c0 + e > r0) sacc[nb][e] = NEGBIG;
                    if (c0 + e > r0 + 8) sacc[nb][2 + e] = NEGBIG;
                }
            }
        }

        // ---- online softmax (log2 domain) ----
        float tm0 = NEGBIG, tm1 = NEGBIG;
#pragma unroll
        for (int nb = 0; nb < 8; nb++) {
            tm0 = fmaxf(tm0, fmaxf(sacc[nb][0], sacc[nb][1]));
            tm1 = fmaxf(tm1, fmaxf(sacc[nb][2], sacc[nb][3]));
        }
        tm0 = fmaxf(tm0, __shfl_xor_sync(0xffffffffu, tm0, 1));
        tm0 = fmaxf(tm0, __shfl_xor_sync(0xffffffffu, tm0, 2));
        tm1 = fmaxf(tm1, __shfl_xor_sync(0xffffffffu, tm1, 1));
        tm1 = fmaxf(tm1, __shfl_xor_sync(0xffffffffu, tm1, 2));

        float mn0 = fmaxf(m0, tm0);
        float mn1 = fmaxf(m1, tm1);
        float corr0 = ex2f(m0 - mn0);
        float corr1 = ex2f(m1 - mn1);
        float rs0 = 0.0f, rs1 = 0.0f;
#pragma unroll
        for (int nb = 0; nb < 8; nb++) {
            sacc[nb][0] = ex2f(sacc[nb][0] - mn0);
            sacc[nb][1] = ex2f(sacc[nb][1] - mn0);
            sacc[nb][2] = ex2f(sacc[nb][2] - mn1);
            sacc[nb][3] = ex2f(sacc[nb][3] - mn1);
            rs0 += sacc[nb][0] + sacc[nb][1];
            rs1 += sacc[nb][2] + sacc[nb][3];
        }
        rs0 += __shfl_xor_sync(0xffffffffu, rs0, 1);
        rs0 += __shfl_xor_sync(0xffffffffu, rs0, 2);
        rs1 += __shfl_xor_sync(0xffffffffu, rs1, 1);
        rs1 += __shfl_xor_sync(0xffffffffu, rs1, 2);

        l0 = l0 * corr0 + rs0;
        l1 = l1 * corr1 + rs1;
        m0 = mn0;
        m1 = mn1;
#pragma unroll
        for (int db = 0; db < 8; db++) {
            oacc[db][0] *= corr0;
            oacc[db][1] *= corr0;
            oacc[db][2] *= corr1;
            oacc[db][3] *= corr1;
        }

        // ---- O += P @ V : single fp16 ----
#pragma unroll
        for (int ks = 0; ks < 4; ks++) {
            uint32_t p16[4];
            p16[0] = h2u(__floats2half2_rn(sacc[2 * ks][0], sacc[2 * ks][1]));
            p16[1] = h2u(__floats2half2_rn(sacc[2 * ks][2], sacc[2 * ks][3]));
            p16[2] = h2u(__floats2half2_rn(sacc[2 * ks + 1][0], sacc[2 * ks + 1][1]));
            p16[3] = h2u(__floats2half2_rn(sacc[2 * ks + 1][2], sacc[2 * ks + 1][3]));
            const uint32_t ko = (uint32_t)(ks * 32);
#pragma unroll
            for (int dbp = 0; dbp < 4; dbp++) {
                const uint32_t ba = bufa + (uint32_t)(dbp * 16 * FRS) + ko;
                uint32_t v0, v1, v2, v3;
                ldsm_x4(v0, v1, v2, v3, ba + OFF_VT);
                mma_fp16(oacc[2 * dbp], p16[0], p16[1], p16[2], p16[3], v0, v1);
                mma_fp16(oacc[2 * dbp + 1], p16[0], p16[1], p16[2], p16[3], v2, v3);
            }
        }
    }

    float inv0 = 1.0f / l0;
    float inv1 = 1.0f / l1;
    int b = bh >> 4;
    int h = bh & 15;
    int t0 = q0 + r0;
    int t1 = t0 + 8;
#pragma unroll
    for (int db = 0; db < 8; db++) {
        int col = h * 64 + db * 8 + 2 * tig;
        float2 y0 = make_float2(oacc[db][0] * inv0, oacc[db][1] * inv0);
        float2 y1 = make_float2(oacc[db][2] * inv1, oacc[db][3] * inv1);
        *(float2*)&g_y[(size_t)(b * TSEQ + t0) * CDIM + col] = y0;
        *(float2*)&g_y[(size_t)(b * TSEQ + t1) * CDIM + col] = y1;
    }
}

// ---------------------------------------------------------------------------
// Launch
// ---------------------------------------------------------------------------
extern "C" void kernel_launch(void* const* d_in, const int* in_sizes, int n_in,
                              void* d_out, int out_size) {
    const float* x      = (const float*)d_in[0];
    const float* w_attn = (const float*)d_in[1];
    const float* b_attn = (const float*)d_in[2];
    const float* w_proj = (const float*)d_in[3];
    const float* b_proj = (const float*)d_in[4];
    float* out = (float*)d_out;

    float *qkv, *y, *xf, *waf, *wpf, *yf;
    float2* rope;
    __half *qf, *kf, *vt;
    cudaGetSymbolAddress((void**)&qkv, g_qkv);
    cudaGetSymbolAddress((void**)&xf, g_xf);
    cudaGetSymbolAddress((void**)&waf, g_waf);
    cudaGetSymbolAddress((void**)&wpf, g_wpf);
    cudaGetSymbolAddress((void**)&yf, g_yf);
    cudaGetSymbolAddress((void**)&qf, g_qf);
    cudaGetSymbolAddress((void**)&kf, g_kf);
    cudaGetSymbolAddress((void**)&vt, g_vt);
    cudaGetSymbolAddress((void**)&y, g_y);
    cudaGetSymbolAddress((void**)&rope, g_rope);

    cudaFuncSetAttribute(gemm_tf32_kernel,
                         cudaFuncAttributeMaxDynamicSharedMemorySize,
                         GEMM_SMEM_BYTES);
    cudaFuncSetAttribute(flash_mma_kernel,
                         cudaFuncAttributeMaxDynamicSharedMemorySize,
                         FLASH_SMEM_BYTES);

    build_rope_kernel<<<(TSEQ * 32 + 255) / 256, 256>>>(rope);

    afrag_kernel<<<(MROWS / 16) * (CDIM / 8) * 32 / 256, 256>>>(x, xf, CDIM);
    bfrag_kernel<<<(CDIM / 8) * (QKVCOLS / 8) * 32 / 256, 256>>>(w_attn, waf, QKVCOLS);
    bfrag_kernel<<<(CDIM / 8) * (CDIM / 8) * 32 / 256, 256>>>(w_proj, wpf, CDIM);

    gemm_tf32_kernel<<<dim3(QKVCOLS / 128, MROWS / 128), 256, GEMM_SMEM_BYTES>>>(
        xf, waf, b_attn, qkv, MROWS, QKVCOLS, CDIM);

    rope_scatter_kernel<<<dim3(TSEQ / 64, BSZ * NHEAD), 256>>>(
        qkv, rope, qf, kf, vt);

    flash_mma_kernel<<<dim3(TSEQ / 64, BSZ * NHEAD), 128, FLASH_SMEM_BYTES>>>(
        qf, kf, vt);

    afrag_kernel<<<(MROWS / 16) * (CDIM / 8) * 32 / 256, 256>>>(y, yf, CDIM);
    gemm_tf32_kernel<<<dim3(CDIM / 128, MROWS / 128), 256, GEMM_SMEM_BYTES>>>(
        yf, wpf, b_proj, out, MROWS, CDIM, CDIM);
}

// round 14
// speedup vs baseline: 2.1005x; 1.3181x over previous
#include <cuda_runtime.h>
#include <cuda_fp16.h>
#include <math.h>
#include <math_constants.h>
#include <stdint.h>

// Problem constants
#define BSZ 2
#define TSEQ 2048
#define CDIM 1024
#define NHEAD 16
#define DHEAD 64
#define MROWS (BSZ * TSEQ)          // 4096
#define QKVCOLS (3 * CDIM)          // 3072

// ---------------------------------------------------------------------------
// Scratch
// ---------------------------------------------------------------------------
__device__ float g_qkv[(size_t)MROWS * QKVCOLS];
// fp16 fragment-order operands (uint4 = one lane's 4 regs of an m16n8k16 frag)
__device__ uint4 g_xf[(size_t)(MROWS / 16) * (CDIM / 16) * 32];
__device__ uint4 g_waf[(size_t)(CDIM / 16) * (QKVCOLS / 16) * 32];
__device__ uint4 g_wpf[(size_t)(CDIM / 16) * (CDIM / 16) * 32];
__device__ uint4 g_yf[(size_t)(MROWS / 16) * (CDIM / 16) * 32];
__device__ __half g_qf[(size_t)BSZ * NHEAD * TSEQ * DHEAD];   // scaled, fp16
__device__ __half g_kf[(size_t)BSZ * NHEAD * TSEQ * DHEAD];   // fp16
__device__ __half g_vt[(size_t)BSZ * NHEAD * DHEAD * TSEQ];   // [bh][d][t], fp16
__device__ float2 g_rope[TSEQ * (DHEAD / 2)];

// ---------------------------------------------------------------------------
// RoPE table
// ---------------------------------------------------------------------------
__global__ void build_rope_kernel(float2* __restrict__ table) {
    int i = blockIdx.x * blockDim.x + threadIdx.x;
    if (i >= TSEQ * 32) return;
    int t = i >> 5;
    int j = i & 31;
    double inv = pow(10000.0, -(double)j / 32.0);
    double ang = (double)t * inv;
    table[i] = make_float2((float)cos(ang), (float)sin(ang));
}

// ---------------------------------------------------------------------------
// Math helpers
// ---------------------------------------------------------------------------
__device__ __forceinline__ float ex2f(float x) {
    float r;
    asm("ex2.approx.ftz.f32 %0, %1;" : "=f"(r) : "f"(x));
    return r;
}
__device__ __forceinline__ uint32_t h2u(__half2 h) {
    return *reinterpret_cast<uint32_t*>(&h);
}
// fp16-accumulate mma: D,C are 2 regs of f16x2
__device__ __forceinline__ void mma_f16acc(uint32_t& d0, uint32_t& d1,
                                           uint32_t a0, uint32_t a1,
                                           uint32_t a2, uint32_t a3,
                                           uint32_t b0, uint32_t b1,
                                           uint32_t c0, uint32_t c1) {
    asm volatile(
        "mma.sync.aligned.m16n8k16.row.col.f16.f16.f16.f16 "
        "{%0,%1}, {%2,%3,%4,%5}, {%6,%7}, {%8,%9};\n"
        : "=r"(d0), "=r"(d1)
        : "r"(a0), "r"(a1), "r"(a2), "r"(a3), "r"(b0), "r"(b1),
          "r"(c0), "r"(c1));
}
__device__ __forceinline__ void mma_fp16(float c[4], uint32_t a0, uint32_t a1,
                                         uint32_t a2, uint32_t a3,
                                         uint32_t b0, uint32_t b1) {
    asm volatile(
        "mma.sync.aligned.m16n8k16.row.col.f32.f16.f16.f32 "
        "{%0,%1,%2,%3}, {%4,%5,%6,%7}, {%8,%9}, {%0,%1,%2,%3};\n"
        : "+f"(c[0]), "+f"(c[1]), "+f"(c[2]), "+f"(c[3])
        : "r"(a0), "r"(a1), "r"(a2), "r"(a3), "r"(b0), "r"(b1));
}
__device__ __forceinline__ void ldsm_x4(uint32_t& r0, uint32_t& r1,
                                        uint32_t& r2, uint32_t& r3,
                                        uint32_t addr) {
    asm volatile(
        "ldmatrix.sync.aligned.m8n8.x4.shared.b16 {%0,%1,%2,%3}, [%4];"
        : "=r"(r0), "=r"(r1), "=r"(r2), "=r"(r3) : "r"(addr));
}
__device__ __forceinline__ uint32_t smem_u32(const void* p) {
    uint32_t a;
    asm("{ .reg .u64 t; cvta.to.shared.u64 t, %1; cvt.u32.u64 %0, t; }"
        : "=r"(a) : "l"(p));
    return a;
}
__device__ __forceinline__ void cp16(uint32_t smem, const void* g) {
    asm volatile("cp.async.ca.shared.global [%0], [%1], 16;"
                 :: "r"(smem), "l"(g) : "memory");
}
#define CP_COMMIT() asm volatile("cp.async.commit_group;" ::: "memory")
#define CP_WAIT0() asm volatile("cp.async.wait_group 0;" ::: "memory")
#define CP_WAIT1() asm volatile("cp.async.wait_group 1;" ::: "memory")
#define CP_WAIT2() asm volatile("cp.async.wait_group 2;" ::: "memory")

// ---------------------------------------------------------------------------
// fp16 A-fragment reorder (round 11, verified): [M][K] -> [M/16][K/16][32]u4
// ---------------------------------------------------------------------------
__global__ void afrag16_kernel(const float* __restrict__ in,
                               uint4* __restrict__ out, int K) {
    int idx = blockIdx.x * 256 + threadIdx.x;
    int lane = idx & 31;
    int blk = idx >> 5;
    int KB = K >> 4;
    int cb = blk % KB, rb = blk / KB;
    int g = lane >> 2, tig = lane & 3;
    const float* p = in + (size_t)(rb * 16 + g) * K + cb * 16 + 2 * tig;
    const size_t r8 = (size_t)8 * K;
    uint4 v;
    v.x = h2u(__floats2half2_rn(p[0], p[1]));
    v.y = h2u(__floats2half2_rn(p[r8], p[r8 + 1]));
    v.z = h2u(__floats2half2_rn(p[8], p[9]));
    v.w = h2u(__floats2half2_rn(p[r8 + 8], p[r8 + 9]));
    out[idx] = v;
}

// ---------------------------------------------------------------------------
// fp16 paired B-fragment reorder (round 11, verified): [K][N] -> [K/16][N/16][32]u4
// ---------------------------------------------------------------------------
__global__ void bfrag16_kernel(const float* __restrict__ in,
                               uint4* __restrict__ out, int N) {
    int idx = blockIdx.x * 256 + threadIdx.x;
    int lane = idx & 31;
    int blk = idx >> 5;
    int NB = N >> 4;
    int nbp = blk % NB, kb = blk / NB;
    int g = lane >> 2, tig = lane & 3;
    const float* p = in + (size_t)(kb * 16 + 2 * tig) * N + nbp * 16 + g;
    const size_t sN = (size_t)N;
    uint4 v;
    v.x = h2u(__floats2half2_rn(p[0], p[sN]));
    v.y = h2u(__floats2half2_rn(p[8 * sN], p[9 * sN]));
    v.z = h2u(__floats2half2_rn(p[8], p[sN + 8]));
    v.w = h2u(__floats2half2_rn(p[8 * sN + 8], p[9 * sN + 8]));
    out[idx] = v;
}

// ---------------------------------------------------------------------------
// FP16 GEMM v6: fp16-ACCUMULATE mma (k32 chunks), fp32 promotion.
// C[M,N] = A@B + bias. 128x128x32 tile, 256 thr (8 warps, 2m x 4n).
// Smem: 3 stages x (A 8KB + B 8KB) = 48KB.
// ---------------------------------------------------------------------------
#define GEMM_SMEM_BYTES 49152

__global__ __launch_bounds__(256, 2)
void gemm_fp16_kernel(const uint4* __restrict__ Af, const uint4* __restrict__ Bf,
                      const float* __restrict__ bias, float* __restrict__ C,
                      int M, int N, int K) {
    extern __shared__ char smg[];
    const uint32_t smb = smem_u32(smg);
    const int tid = threadIdx.x;
    const int lane = tid & 31;
    const int warp = tid >> 5;
    const int wm = warp >> 2;
    const int wn = warp & 3;
    const int g = lane >> 2;
    const int tig = lane & 3;
    const int row0 = blockIdx.y * 128;
    const int col0 = blockIdx.x * 128;
    const int KB16 = K >> 4;
    const int NB16 = N >> 4;
    const int rb0 = row0 >> 4;
    const int nbp0 = col0 >> 4;

    float acc[4][4][4];
#pragma unroll
    for (int im = 0; im < 4; im++)
#pragma unroll
        for (int in = 0; in < 4; in++)
#pragma unroll
            for (int r = 0; r < 4; r++) acc[im][in][r] = 0.0f;

    int a_rblk[2], a_kblk[2], a_l[2];
    int b_blk[2], b_kblk[2], b_nbp[2], b_l[2];
#pragma unroll
    for (int s = 0; s < 2; s++) {
        int u = tid + s * 256;
        int ablk = u >> 5;
        a_rblk[s] = ablk >> 1;
        a_kblk[s] = ablk & 1;
        a_l[s] = u & 31;
        b_blk[s] = u >> 5;
        b_kblk[s] = u >> 8;
        b_nbp[s] = (u >> 5) & 7;
        b_l[s] = u & 31;
    }

    const int nT = K / 32;

#define GEMM_ISSUE(tt) do {                                                    \
        const int kbg = (tt) * 2;                                              \
        const int st = (tt) % 3;                                               \
        const uint32_t ao = (uint32_t)(st * 8192);                             \
        const uint32_t bo = 24576u + (uint32_t)(st * 8192);                    \
        _Pragma("unroll")                                                      \
        for (int s = 0; s < 2; s++) {                                          \
            cp16(smb + ao + (uint32_t)((a_rblk[s] * 2 + a_kblk[s]) * 512 + a_l[s] * 16), \
                 Af + (((size_t)(rb0 + a_rblk[s]) * KB16 + kbg + a_kblk[s]) << 5) + a_l[s]); \
            cp16(smb + bo + (uint32_t)(b_blk[s] * 512 + b_l[s] * 16),          \
                 Bf + (((size_t)(kbg + b_kblk[s]) * NB16 + nbp0 + b_nbp[s]) << 5) + b_l[s]); \
        }                                                                      \
        CP_COMMIT();                                                           \
    } while (0)

    GEMM_ISSUE(0);
    GEMM_ISSUE(1);

    for (int t = 0; t < nT; t++) {
        if (t + 2 < nT) {
            GEMM_ISSUE(t + 2);
            CP_WAIT2();
        } else if (t + 1 < nT) {
            CP_WAIT1();
        } else {
            CP_WAIT0();
        }
        __syncthreads();

        const char* As = smg + (t % 3) * 8192;
        const char* Bs = smg + 24576 + (t % 3) * 8192;

        // load both k16 sub-tiles' fragments
        uint4 af[2][4];
        uint4 b4[2][2];
#pragma unroll
        for (int kk = 0; kk < 2; kk++) {
#pragma unroll
            for (int im = 0; im < 4; im++)
                af[kk][im] = *(const uint4*)(As + ((wm * 4 + im) * 2 + kk) * 512 + lane * 16);
#pragma unroll
            for (int p = 0; p < 2; p++)
                b4[kk][p] = *(const uint4*)(Bs + (kk * 8 + wn * 2 + p) * 512 + lane * 16);
        }

        // chunk-accumulate in fp16 (2 mma), promote to fp32
#pragma unroll
        for (int im = 0; im < 4; im++) {
#pragma unroll
            for (int p = 0; p < 2; p++) {
#pragma unroll
                for (int hh = 0; hh < 2; hh++) {
                    uint32_t bk0_0 = hh ? b4[0][p].z : b4[0][p].x;
                    uint32_t bk0_1 = hh ? b4[0][p].w : b4[0][p].y;
                    uint32_t bk1_0 = hh ? b4[1][p].z : b4[1][p].x;
                    uint32_t bk1_1 = hh ? b4[1][p].w : b4[1][p].y;
                    uint32_t d0, d1;
                    mma_f16acc(d0, d1, af[0][im].x, af[0][im].y, af[0][im].z,
                               af[0][im].w, bk0_0, bk0_1, 0u, 0u);
                    mma_f16acc(d0, d1, af[1][im].x, af[1][im].y, af[1][im].z,
                               af[1][im].w, bk1_0, bk1_1, d0, d1);
                    float* a4 = acc[im][2 * p + hh];
                    float2 f0 = __half22float2(*reinterpret_cast<__half2*>(&d0));
                    float2 f1 = __half22float2(*reinterpret_cast<__half2*>(&d1));
                    a4[0] += f0.x;
                    a4[1] += f0.y;
                    a4[2] += f1.x;
                    a4[3] += f1.y;
                }
            }
        }
        __syncthreads();
    }

    // epilogue: rows g + {0,8}, cols 2*tig + {0,1}
#pragma unroll
    for (int im = 0; im < 4; im++) {
        int r = row0 + wm * 64 + im * 16 + g;
#pragma unroll
        for (int in = 0; in < 4; in++) {
            int c = col0 + wn * 32 + in * 8 + tig * 2;
            float b0 = bias[c], b1 = bias[c + 1];
            float2 v0 = make_float2(acc[im][in][0] + b0, acc[im][in][1] + b1);
            float2 v1 = make_float2(acc[im][in][2] + b0, acc[im][in][3] + b1);
            *(float2*)&C[(size_t)r * N + c] = v0;
            *(float2*)&C[(size_t)(r + 8) * N + c] = v1;
        }
    }
#undef GEMM_ISSUE
}

// ---------------------------------------------------------------------------
// RoPE + scatter: q (scaled) / k fp16 [bh][t][d], v fp16 transposed [bh][d][t]
// ---------------------------------------------------------------------------
__global__ __launch_bounds__(256)
void rope_scatter_kernel(const float* __restrict__ qkv,
                         const float2* __restrict__ rope,
                         __half* __restrict__ qf, __half* __restrict__ kf,
                         __half* __restrict__ vt) {
    __shared__ __half vsh[64][66];

    int bh = blockIdx.y;
    int tb = blockIdx.x * 64;
    int b = bh >> 4;
    int h = bh & 15;
    int tid = threadIdx.x;

    const float SCL = 0.125f * 1.4426950408889634f;

#pragma unroll
    for (int e = 0; e < 16; e++) {
        int idx = tid + e * 256;
        int tl = idx >> 6;
        int d = idx & 63;
        int t = tb + tl;
        size_t base = (size_t)(b * TSEQ + t) * QKVCOLS + h * DHEAD;
        float2 cs = rope[t * 32 + (d & 31)];

        float qv = qkv[base + d];
        float kv = qkv[base + CDIM + d];
        float vv = qkv[base + 2 * CDIM + d];
        int dp = (d < 32) ? d + 32 : d - 32;
        float sgn = (d < 32) ? -1.0f : 1.0f;
        float qr = qkv[base + dp];
        float kr = qkv[base + CDIM + dp];

        float qrot = (qv * cs.x + sgn * qr * cs.y) * SCL;
        float krot = kv * cs.x + sgn * kr * cs.y;

        size_t o = ((size_t)bh * TSEQ + t) * DHEAD + d;
        qf[o] = __float2half_rn(qrot);
        kf[o] = __float2half_rn(krot);
        vsh[d][tl] = __float2half_rn(vv);
    }
    __syncthreads();
#pragma unroll
    for (int e = 0; e < 16; e++) {
        int idx = tid + e * 256;
        int d = idx >> 6;
        int tl = idx & 63;
        vt[((size_t)bh * DHEAD + d) * TSEQ + tb + tl] = vsh[d][tl];
    }
}

// ---------------------------------------------------------------------------
// Flash attention v8 (round 13) + fp16 A-frag epilogue (round 11 mapping)
// ---------------------------------------------------------------------------
#define FRS 144
#define OFF_K 0
#define OFF_VT 9216
#define BUFB 18432
#define FLASH_SMEM_BYTES (2 * BUFB)   // 36864

#define NEGBIG (-1e30f)

__global__ __launch_bounds__(128, 3)
void flash_mma_kernel(const __half* __restrict__ QF,
                      const __half* __restrict__ KF,
                      const __half* __restrict__ VT) {
    extern __shared__ char smc[];
    const uint32_t smb = smem_u32(smc);

    int bh = blockIdx.y;
    int qt = gridDim.x - 1 - blockIdx.x;
    int q0 = qt * 64;

    int tid = threadIdx.x;
    int lane = tid & 31;
    int w = tid >> 5;
    int g = lane >> 2;
    int tig = lane & 3;
    const int r0 = w * 16 + g;

    const int jj = lane & 7;
    const uint32_t ldsm_base =
        (uint32_t)((jj + ((lane >> 4) & 1) * 8) * FRS + ((lane >> 3) & 1) * 16);

    const __half* KFg = KF + (size_t)bh * TSEQ * DHEAD;
    const __half* VTg = VT + (size_t)bh * DHEAD * TSEQ;

    {
#pragma unroll
        for (int s = 0; s < 4; s++) {
            int f = tid + s * 128;
            int r = f >> 3;
            int c = (f & 7) * 8;
            uint32_t ro = (uint32_t)(r * FRS + c * 2);
            cp16(smb + OFF_K + ro, KFg + (size_t)r * DHEAD + c);
            cp16(smb + OFF_VT + ro, VTg + (size_t)r * TSEQ + c);
        }
        CP_COMMIT();
    }

    uint32_t qa[4][4];
    {
        const __half* Qg = QF + ((size_t)bh * TSEQ + q0 + r0) * DHEAD;
#pragma unroll
        for (int ks = 0; ks < 4; ks++) {
            int c0 = ks * 16 + 2 * tig;
            qa[ks][0] = *(const uint32_t*)(Qg + c0);
            qa[ks][1] = *(const uint32_t*)(Qg + 8 * DHEAD + c0);
            qa[ks][2] = *(const uint32_t*)(Qg + c0 + 8);
            qa[ks][3] = *(const uint32_t*)(Qg + 8 * DHEAD + c0 + 8);
        }
    }

    float oacc[8][4];
#pragma unroll
    for (int db = 0; db < 8; db++)
#pragma unroll
        for (int r = 0; r < 4; r++) oacc[db][r] = 0.0f;
    float m0 = NEGBIG, m1 = NEGBIG, l0 = 0.0f, l1 = 0.0f;

    for (int jt = 0; jt <= qt; jt++) {
        CP_WAIT0();
        __syncthreads();

        if (jt < qt) {
            int k0n = (jt + 1) * 64;
            uint32_t nb_ = smb + ((jt + 1) & 1) * BUFB;
#pragma unroll
            for (int s = 0; s < 4; s++) {
                int f = tid + s * 128;
                int r = f >> 3;
                int c = (f & 7) * 8;
                uint32_t ro = (uint32_t)(r * FRS + c * 2);
                cp16(nb_ + OFF_K + ro, KFg + (size_t)(k0n + r) * DHEAD + c);
                cp16(nb_ + OFF_VT + ro, VTg + (size_t)r * TSEQ + k0n + c);
            }
            CP_COMMIT();
        }

        const uint32_t bufa = smb + (jt & 1) * BUFB + ldsm_base;

        float sacc[8][4];
#pragma unroll
        for (int nb = 0; nb < 8; nb++)
#pragma unroll
            for (int r = 0; r < 4; r++) sacc[nb][r] = 0.0f;

#pragma unroll
        for (int ks = 0; ks < 4; ks++) {
            const uint32_t ko = (uint32_t)(ks * 32);
#pragma unroll
            for (int nbp = 0; nbp < 4; nbp++) {
                const uint32_t ba = bufa + (uint32_t)(nbp * 16 * FRS) + ko;
                uint32_t b0, b1, b2, b3;
                ldsm_x4(b0, b1, b2, b3, ba + OFF_K);
                mma_fp16(sacc[2 * nbp], qa[ks][0], qa[ks][1], qa[ks][2], qa[ks][3], b0, b1);
                mma_fp16(sacc[2 * nbp + 1], qa[ks][0], qa[ks][1], qa[ks][2], qa[ks][3], b2, b3);
            }
        }

        if (jt == qt) {
#pragma unroll
            for (int nb = 0; nb < 8; nb++) {
                int c0 = nb * 8 + 2 * tig;
#pragma unroll
                for (int e = 0; e < 2; e++) {
                    if (c0 + e > r0) sacc[nb][e] = NEGBIG;
                    if (c0 + e > r0 + 8) sacc[nb][2 + e] = NEGBIG;
                }
            }
        }

        float tm0 = NEGBIG, tm1 = NEGBIG;
#pragma unroll
        for (int nb = 0; nb < 8; nb++) {
            tm0 = fmaxf(tm0, fmaxf(sacc[nb][0], sacc[nb][1]));
            tm1 = fmaxf(tm1, fmaxf(sacc[nb][2], sacc[nb][3]));
        }
        tm0 = fmaxf(tm0, __shfl_xor_sync(0xffffffffu, tm0, 1));
        tm0 = fmaxf(tm0, __shfl_xor_sync(0xffffffffu, tm0, 2));
        tm1 = fmaxf(tm1, __shfl_xor_sync(0xffffffffu, tm1, 1));
        tm1 = fmaxf(tm1, __shfl_xor_sync(0xffffffffu, tm1, 2));

        float mn0 = fmaxf(m0, tm0);
        float mn1 = fmaxf(m1, tm1);
        float corr0 = ex2f(m0 - mn0);
        float corr1 = ex2f(m1 - mn1);
        float rs0 = 0.0f, rs1 = 0.0f;
#pragma unroll
        for (int nb = 0; nb < 8; nb++) {
            sacc[nb][0] = ex2f(sacc[nb][0] - mn0);
            sacc[nb][1] = ex2f(sacc[nb][1] - mn0);
            sacc[nb][2] = ex2f(sacc[nb][2] - mn1);
            sacc[nb][3] = ex2f(sacc[nb][3] - mn1);
            rs0 += sacc[nb][0] + sacc[nb][1];
            rs1 += sacc[nb][2] + sacc[nb][3];
        }
        rs0 += __shfl_xor_sync(0xffffffffu, rs0, 1);
        rs0 += __shfl_xor_sync(0xffffffffu, rs0, 2);
        rs1 += __shfl_xor_sync(0xffffffffu, rs1, 1);
        rs1 += __shfl_xor_sync(0xffffffffu, rs1, 2);

        l0 = l0 * corr0 + rs0;
        l1 = l1 * corr1 + rs1;
        m0 = mn0;
        m1 = mn1;
#pragma unroll
        for (int db = 0; db < 8; db++) {
            oacc[db][0] *= corr0;
            oacc[db][1] *= corr0;
            oacc[db][2] *= corr1;
            oacc[db][3] *= corr1;
        }

#pragma unroll
        for (int ks = 0; ks < 4; ks++) {
            uint32_t p16[4];
            p16[0] = h2u(__floats2half2_rn(sacc[2 * ks][0], sacc[2 * ks][1]));
            p16[1] = h2u(__floats2half2_rn(sacc[2 * ks][2], sacc[2 * ks][3]));
            p16[2] = h2u(__floats2half2_rn(sacc[2 * ks + 1][0], sacc[2 * ks + 1][1]));
            p16[3] = h2u(__floats2half2_rn(sacc[2 * ks + 1][2], sacc[2 * ks + 1][3]));
            const uint32_t ko = (uint32_t)(ks * 32);
#pragma unroll
            for (int dbp = 0; dbp < 4; dbp++) {
                const uint32_t ba = bufa + (uint32_t)(dbp * 16 * FRS) + ko;
                uint32_t v0, v1, v2, v3;
                ldsm_x4(v0, v1, v2, v3, ba + OFF_VT);
                mma_fp16(oacc[2 * dbp], p16[0], p16[1], p16[2], p16[3], v0, v1);
                mma_fp16(oacc[2 * dbp + 1], p16[0], p16[1], p16[2], p16[3], v2, v3);
            }
        }
    }

    // ---- finalize: write y as fp16 A-fragments (round-11-verified layout) ----
    float inv0 = 1.0f / l0;
    float inv1 = 1.0f / l1;
    int b = bh >> 4;
    int h = bh & 15;
    const size_t rb = (size_t)((b * TSEQ + q0) >> 4) + w;
#pragma unroll
    for (int dbp = 0; dbp < 4; dbp++) {
        int cb = h * 4 + dbp;
        uint4 v;
        v.x = h2u(__floats2half2_rn(oacc[2 * dbp][0] * inv0, oacc[2 * dbp][1] * inv0));
        v.y = h2u(__floats2half2_rn(oacc[2 * dbp][2] * inv1, oacc[2 * dbp][3] * inv1));
        v.z = h2u(__floats2half2_rn(oacc[2 * dbp + 1][0] * inv0, oacc[2 * dbp + 1][1] * inv0));
        v.w = h2u(__floats2half2_rn(oacc[2 * dbp + 1][2] * inv1, oacc[2 * dbp + 1][3] * inv1));
        g_yf[(rb * 64 + cb) * 32 + lane] = v;
    }
}

// ---------------------------------------------------------------------------
// Launch
// ---------------------------------------------------------------------------
extern "C" void kernel_launch(void* const* d_in, const int* in_sizes, int n_in,
                              void* d_out, int out_size) {
    const float* x      = (const float*)d_in[0];
    const float* w_attn = (const float*)d_in[1];
    const float* b_attn = (const float*)d_in[2];
    const float* w_proj = (const float*)d_in[3];
    const float* b_proj = (const float*)d_in[4];
    float* out = (float*)d_out;

    float* qkv;
    uint4 *xf, *waf, *wpf, *yf;
    float2* rope;
    __half *qf, *kf, *vt;
    cudaGetSymbolAddress((void**)&qkv, g_qkv);
    cudaGetSymbolAddress((void**)&xf, g_xf);
    cudaGetSymbolAddress((void**)&waf, g_waf);
    cudaGetSymbolAddress((void**)&wpf, g_wpf);
    cudaGetSymbolAddress((void**)&yf, g_yf);
    cudaGetSymbolAddress((void**)&qf, g_qf);
    cudaGetSymbolAddress((void**)&kf, g_kf);
    cudaGetSymbolAddress((void**)&vt, g_vt);
    cudaGetSymbolAddress((void**)&rope, g_rope);

    cudaFuncSetAttribute(gemm_fp16_kernel,
                         cudaFuncAttributeMaxDynamicSharedMemorySize,
                         GEMM_SMEM_BYTES);
    cudaFuncSetAttribute(flash_mma_kernel,
                         cudaFuncAttributeMaxDynamicSharedMemorySize,
                         FLASH_SMEM_BYTES);

    build_rope_kernel<<<(TSEQ * 32 + 255) / 256, 256>>>(rope);

    afrag16_kernel<<<(MROWS / 16) * (CDIM / 16) * 32 / 256, 256>>>(x, xf, CDIM);
    bfrag16_kernel<<<(CDIM / 16) * (QKVCOLS / 16) * 32 / 256, 256>>>(w_attn, waf, QKVCOLS);
    bfrag16_kernel<<<(CDIM / 16) * (CDIM / 16) * 32 / 256, 256>>>(w_proj, wpf, CDIM);

    gemm_fp16_kernel<<<dim3(QKVCOLS / 128, MROWS / 128), 256, GEMM_SMEM_BYTES>>>(
        xf, waf, b_attn, qkv, MROWS, QKVCOLS, CDIM);

    rope_scatter_kernel<<<dim3(TSEQ / 64, BSZ * NHEAD), 256>>>(
        qkv, rope, qf, kf, vt);

    flash_mma_kernel<<<dim3(TSEQ / 64, BSZ * NHEAD), 128, FLASH_SMEM_BYTES>>>(
        qf, kf, vt);

    gemm_fp16_kernel<<<dim3(CDIM / 128, MROWS / 128), 256, GEMM_SMEM_BYTES>>>(
        yf, wpf, b_proj, out, MROWS, CDIM, CDIM);
}

// round 15
// speedup vs baseline: 2.1447x; 1.0210x over previous
#include <cuda_runtime.h>
#include <cuda_fp16.h>
#include <math.h>
#include <math_constants.h>
#include <stdint.h>

// Problem constants
#define BSZ 2
#define TSEQ 2048
#define CDIM 1024
#define NHEAD 16
#define DHEAD 64
#define MROWS (BSZ * TSEQ)          // 4096
#define QKVCOLS (3 * CDIM)          // 3072

// ---------------------------------------------------------------------------
// Scratch
// ---------------------------------------------------------------------------
__device__ uint4 g_xf[(size_t)(MROWS / 16) * (CDIM / 16) * 32];
__device__ uint4 g_waf[(size_t)(CDIM / 16) * (QKVCOLS / 16) * 32];
__device__ uint4 g_wpf[(size_t)(CDIM / 16) * (CDIM / 16) * 32];
__device__ uint4 g_yf[(size_t)(MROWS / 16) * (CDIM / 16) * 32];
__device__ __half g_qf[(size_t)BSZ * NHEAD * TSEQ * DHEAD];   // scaled, fp16
__device__ __half g_kf[(size_t)BSZ * NHEAD * TSEQ * DHEAD];   // fp16
__device__ __half g_vt[(size_t)BSZ * NHEAD * DHEAD * TSEQ];   // [bh][d][t], fp16
__device__ float2 g_rope[TSEQ * (DHEAD / 2)];

// ---------------------------------------------------------------------------
// RoPE table
// ---------------------------------------------------------------------------
__global__ void build_rope_kernel(float2* __restrict__ table) {
    int i = blockIdx.x * blockDim.x + threadIdx.x;
    if (i >= TSEQ * 32) return;
    int t = i >> 5;
    int j = i & 31;
    double inv = pow(10000.0, -(double)j / 32.0);
    double ang = (double)t * inv;
    table[i] = make_float2((float)cos(ang), (float)sin(ang));
}

// ---------------------------------------------------------------------------
// Math helpers
// ---------------------------------------------------------------------------
__device__ __forceinline__ float ex2f(float x) {
    float r;
    asm("ex2.approx.ftz.f32 %0, %1;" : "=f"(r) : "f"(x));
    return r;
}
__device__ __forceinline__ uint32_t h2u(__half2 h) {
    return *reinterpret_cast<uint32_t*>(&h);
}
__device__ __forceinline__ void mma_f16acc(uint32_t& d0, uint32_t& d1,
                                           uint32_t a0, uint32_t a1,
                                           uint32_t a2, uint32_t a3,
                                           uint32_t b0, uint32_t b1,
                                           uint32_t c0, uint32_t c1) {
    asm volatile(
        "mma.sync.aligned.m16n8k16.row.col.f16.f16.f16.f16 "
        "{%0,%1}, {%2,%3,%4,%5}, {%6,%7}, {%8,%9};\n"
        : "=r"(d0), "=r"(d1)
        : "r"(a0), "r"(a1), "r"(a2), "r"(a3), "r"(b0), "r"(b1),
          "r"(c0), "r"(c1));
}
__device__ __forceinline__ void mma_fp16(float c[4], uint32_t a0, uint32_t a1,
                                         uint32_t a2, uint32_t a3,
                                         uint32_t b0, uint32_t b1) {
    asm volatile(
        "mma.sync.aligned.m16n8k16.row.col.f32.f16.f16.f32 "
        "{%0,%1,%2,%3}, {%4,%5,%6,%7}, {%8,%9}, {%0,%1,%2,%3};\n"
        : "+f"(c[0]), "+f"(c[1]), "+f"(c[2]), "+f"(c[3])
        : "r"(a0), "r"(a1), "r"(a2), "r"(a3), "r"(b0), "r"(b1));
}
__device__ __forceinline__ void ldsm_x4(uint32_t& r0, uint32_t& r1,
                                        uint32_t& r2, uint32_t& r3,
                                        uint32_t addr) {
    asm volatile(
        "ldmatrix.sync.aligned.m8n8.x4.shared.b16 {%0,%1,%2,%3}, [%4];"
        : "=r"(r0), "=r"(r1), "=r"(r2), "=r"(r3) : "r"(addr));
}
__device__ __forceinline__ uint32_t smem_u32(const void* p) {
    uint32_t a;
    asm("{ .reg .u64 t; cvta.to.shared.u64 t, %1; cvt.u32.u64 %0, t; }"
        : "=r"(a) : "l"(p));
    return a;
}
__device__ __forceinline__ void cp16(uint32_t smem, const void* g) {
    asm volatile("cp.async.ca.shared.global [%0], [%1], 16;"
                 :: "r"(smem), "l"(g) : "memory");
}
#define CP_COMMIT() asm volatile("cp.async.commit_group;" ::: "memory")
#define CP_WAIT0() asm volatile("cp.async.wait_group 0;" ::: "memory")
#define CP_WAIT1() asm volatile("cp.async.wait_group 1;" ::: "memory")
#define CP_WAIT2() asm volatile("cp.async.wait_group 2;" ::: "memory")

// ---------------------------------------------------------------------------
// fp16 A-fragment reorder: [M][K] -> [M/16][K/16][32]u4
// ---------------------------------------------------------------------------
__global__ void afrag16_kernel(const float* __restrict__ in,
                               uint4* __restrict__ out, int K) {
    int idx = blockIdx.x * 256 + threadIdx.x;
    int lane = idx & 31;
    int blk = idx >> 5;
    int KB = K >> 4;
    int cb = blk % KB, rb = blk / KB;
    int g = lane >> 2, tig = lane & 3;
    const float* p = in + (size_t)(rb * 16 + g) * K + cb * 16 + 2 * tig;
    const size_t r8 = (size_t)8 * K;
    uint4 v;
    v.x = h2u(__floats2half2_rn(p[0], p[1]));
    v.y = h2u(__floats2half2_rn(p[r8], p[r8 + 1]));
    v.z = h2u(__floats2half2_rn(p[8], p[9]));
    v.w = h2u(__floats2half2_rn(p[r8 + 8], p[r8 + 9]));
    out[idx] = v;
}

// ---------------------------------------------------------------------------
// fp16 paired B-fragment reorder: [K][N] -> [K/16][N/16][32]u4
// ---------------------------------------------------------------------------
__global__ void bfrag16_kernel(const float* __restrict__ in,
                               uint4* __restrict__ out, int N) {
    int idx = blockIdx.x * 256 + threadIdx.x;
    int lane = idx & 31;
    int blk = idx >> 5;
    int NB = N >> 4;
    int nbp = blk % NB, kb = blk / NB;
    int g = lane >> 2, tig = lane & 3;
    const float* p = in + (size_t)(kb * 16 + 2 * tig) * N + nbp * 16 + g;
    const size_t sN = (size_t)N;
    uint4 v;
    v.x = h2u(__floats2half2_rn(p[0], p[sN]));
    v.y = h2u(__floats2half2_rn(p[8 * sN], p[9 * sN]));
    v.z = h2u(__floats2half2_rn(p[8], p[sN + 8]));
    v.w = h2u(__floats2half2_rn(p[8 * sN + 8], p[9 * sN + 8]));
    out[idx] = v;
}

// ---------------------------------------------------------------------------
// FP16 GEMM v7: fp16-acc mma (k32 chunks -> fp32), 3-stage cp.async.
// mode 0: plain fp32 store to C (+bias).
// mode 1: fused QKV epilogue — stage tile in smem, apply RoPE, write
//         q (scaled) / k fp16 [bh][t][d] and v fp16 transposed [bh][d][t].
// Smem: pipeline 48KB; mode-1 staging 128x133 fp32 = 68096 B (reused).
// ---------------------------------------------------------------------------
#define GEMM_SMEM_BYTES 68096
#define STG_S 133

__global__ __launch_bounds__(256, 2)
void gemm_fp16_kernel(const uint4* __restrict__ Af, const uint4* __restrict__ Bf,
                      const float* __restrict__ bias, float* __restrict__ C,
                      int M, int N, int K, int mode) {
    extern __shared__ char smg[];
    const uint32_t smb = smem_u32(smg);
    const int tid = threadIdx.x;
    const int lane = tid & 31;
    const int warp = tid >> 5;
    const int wm = warp >> 2;
    const int wn = warp & 3;
    const int g = lane >> 2;
    const int tig = lane & 3;
    const int row0 = blockIdx.y * 128;
    const int col0 = blockIdx.x * 128;
    const int KB16 = K >> 4;
    const int NB16 = N >> 4;
    const int rb0 = row0 >> 4;
    const int nbp0 = col0 >> 4;

    float acc[4][4][4];
#pragma unroll
    for (int im = 0; im < 4; im++)
#pragma unroll
        for (int in = 0; in < 4; in++)
#pragma unroll
            for (int r = 0; r < 4; r++) acc[im][in][r] = 0.0f;

    int a_rblk[2], a_kblk[2], a_l[2];
    int b_blk[2], b_kblk[2], b_nbp[2], b_l[2];
#pragma unroll
    for (int s = 0; s < 2; s++) {
        int u = tid + s * 256;
        int ablk = u >> 5;
        a_rblk[s] = ablk >> 1;
        a_kblk[s] = ablk & 1;
        a_l[s] = u & 31;
        b_blk[s] = u >> 5;
        b_kblk[s] = u >> 8;
        b_nbp[s] = (u >> 5) & 7;
        b_l[s] = u & 31;
    }

    const int nT = K / 32;

#define GEMM_ISSUE(tt) do {                                                    \
        const int kbg = (tt) * 2;                                              \
        const int st = (tt) % 3;                                               \
        const uint32_t ao = (uint32_t)(st * 8192);                             \
        const uint32_t bo = 24576u + (uint32_t)(st * 8192);                    \
        _Pragma("unroll")                                                      \
        for (int s = 0; s < 2; s++) {                                          \
            cp16(smb + ao + (uint32_t)((a_rblk[s] * 2 + a_kblk[s]) * 512 + a_l[s] * 16), \
                 Af + (((size_t)(rb0 + a_rblk[s]) * KB16 + kbg + a_kblk[s]) << 5) + a_l[s]); \
            cp16(smb + bo + (uint32_t)(b_blk[s] * 512 + b_l[s] * 16),          \
                 Bf + (((size_t)(kbg + b_kblk[s]) * NB16 + nbp0 + b_nbp[s]) << 5) + b_l[s]); \
        }                                                                      \
        CP_COMMIT();                                                           \
    } while (0)

    GEMM_ISSUE(0);
    GEMM_ISSUE(1);

    for (int t = 0; t < nT; t++) {
        if (t + 2 < nT) {
            GEMM_ISSUE(t + 2);
            CP_WAIT2();
        } else if (t + 1 < nT) {
            CP_WAIT1();
        } else {
            CP_WAIT0();
        }
        __syncthreads();

        const char* As = smg + (t % 3) * 8192;
        const char* Bs = smg + 24576 + (t % 3) * 8192;

        uint4 af[2][4];
        uint4 b4[2][2];
#pragma unroll
        for (int kk = 0; kk < 2; kk++) {
#pragma unroll
            for (int im = 0; im < 4; im++)
                af[kk][im] = *(const uint4*)(As + ((wm * 4 + im) * 2 + kk) * 512 + lane * 16);
#pragma unroll
            for (int p = 0; p < 2; p++)
                b4[kk][p] = *(const uint4*)(Bs + (kk * 8 + wn * 2 + p) * 512 + lane * 16);
        }

#pragma unroll
        for (int im = 0; im < 4; im++) {
#pragma unroll
            for (int p = 0; p < 2; p++) {
#pragma unroll
                for (int hh = 0; hh < 2; hh++) {
                    uint32_t bk0_0 = hh ? b4[0][p].z : b4[0][p].x;
                    uint32_t bk0_1 = hh ? b4[0][p].w : b4[0][p].y;
                    uint32_t bk1_0 = hh ? b4[1][p].z : b4[1][p].x;
                    uint32_t bk1_1 = hh ? b4[1][p].w : b4[1][p].y;
                    uint32_t d0, d1;
                    mma_f16acc(d0, d1, af[0][im].x, af[0][im].y, af[0][im].z,
                               af[0][im].w, bk0_0, bk0_1, 0u, 0u);
                    mma_f16acc(d0, d1, af[1][im].x, af[1][im].y, af[1][im].z,
                               af[1][im].w, bk1_0, bk1_1, d0, d1);
                    float* a4 = acc[im][2 * p + hh];
                    float2 f0 = __half22float2(*reinterpret_cast<__half2*>(&d0));
                    float2 f1 = __half22float2(*reinterpret_cast<__half2*>(&d1));
                    a4[0] += f0.x;
                    a4[1] += f0.y;
                    a4[2] += f1.x;
                    a4[3] += f1.y;
                }
            }
        }
        __syncthreads();
    }

    if (mode == 0) {
        // plain epilogue: rows g + {0,8}, cols 2*tig + {0,1}
#pragma unroll
        for (int im = 0; im < 4; im++) {
            int r = row0 + wm * 64 + im * 16 + g;
#pragma unroll
            for (int in = 0; in < 4; in++) {
                int c = col0 + wn * 32 + in * 8 + tig * 2;
                float b0 = bias[c], b1 = bias[c + 1];
                float2 v0 = make_float2(acc[im][in][0] + b0, acc[im][in][1] + b1);
                float2 v1 = make_float2(acc[im][in][2] + b0, acc[im][in][3] + b1);
                *(float2*)&C[(size_t)r * N + c] = v0;
                *(float2*)&C[(size_t)(r + 8) * N + c] = v1;
            }
        }
        return;
    }

    // ---- mode 1: fused QKV epilogue ----
    float* stg = (float*)smg;
#pragma unroll
    for (int im = 0; im < 4; im++) {
        int rl = wm * 64 + im * 16 + g;
#pragma unroll
        for (int in = 0; in < 4; in++) {
            int cl = wn * 32 + in * 8 + tig * 2;
            float b0 = bias[col0 + cl], b1 = bias[col0 + cl + 1];
            stg[rl * STG_S + cl] = acc[im][in][0] + b0;
            stg[rl * STG_S + cl + 1] = acc[im][in][1] + b1;
            stg[(rl + 8) * STG_S + cl] = acc[im][in][2] + b0;
            stg[(rl + 8) * STG_S + cl + 1] = acc[im][in][3] + b1;
        }
    }
    __syncthreads();

    const int b = row0 >> 11;          // 2048 rows per batch
    const int tb = row0 & 2047;
    const float SCL = 0.125f * 1.4426950408889634f;

    if (col0 < 2048) {
        // q or k region: apply RoPE, write [bh][t][d] fp16
        const bool isq = (col0 < 1024);
        __half* dst = isq ? g_qf : g_kf;
        const float scl = isq ? SCL : 1.0f;
        const int cbase = col0 & 1023;
        for (int e = tid; e < 8192; e += 256) {
            int tl = e >> 6;
            int c2 = (e & 63) << 1;
            int colg = cbase + c2;
            int h = colg >> 6;
            int d = colg & 63;
            int t = tb + tl;
            float2 cs0 = g_rope[t * 32 + (d & 31)];
            float2 cs1 = g_rope[t * 32 + ((d + 1) & 31)];
            int cp = (d < 32) ? c2 + 32 : c2 - 32;
            float sgn = (d < 32) ? -1.0f : 1.0f;
            float v0 = stg[tl * STG_S + c2];
            float v1 = stg[tl * STG_S + c2 + 1];
            float p0 = stg[tl * STG_S + cp];
            float p1 = stg[tl * STG_S + cp + 1];
            float q0 = (v0 * cs0.x + sgn * p0 * cs0.y) * scl;
            float q1 = (v1 * cs1.x + sgn * p1 * cs1.y) * scl;
            *(__half2*)&dst[(((size_t)(b * NHEAD + h)) * TSEQ + t) * DHEAD + d] =
                __floats2half2_rn(q0, q1);
        }
    } else {
        // v region: transpose, write [bh][d][t] fp16
        const int cbase = col0 - 2048;
        for (int e = tid; e < 8192; e += 256) {
            int dl = e >> 6;
            int t2 = (e & 63) << 1;
            int colg = cbase + dl;
            int h = colg >> 6;
            int d = colg & 63;
            float v0 = stg[t2 * STG_S + dl];
            float v1 = stg[(t2 + 1) * STG_S + dl];
            *(__half2*)&g_vt[(((size_t)(b * NHEAD + h)) * DHEAD + d) * TSEQ + tb + t2] =
                __floats2half2_rn(v0, v1);
        }
    }
#undef GEMM_ISSUE
}

// ---------------------------------------------------------------------------
// Flash attention v8 (round 13/14, unchanged): S + PV single fp16 mma,
// fp16 A-frag epilogue for y.
// ---------------------------------------------------------------------------
#define FRS 144
#define OFF_K 0
#define OFF_VT 9216
#define BUFB 18432
#define FLASH_SMEM_BYTES (2 * BUFB)

#define NEGBIG (-1e30f)

__global__ __launch_bounds__(128, 3)
void flash_mma_kernel(const __half* __restrict__ QF,
                      const __half* __restrict__ KF,
                      const __half* __restrict__ VT) {
    extern __shared__ char smc[];
    const uint32_t smb = smem_u32(smc);

    int bh = blockIdx.y;
    int qt = gridDim.x - 1 - blockIdx.x;
    int q0 = qt * 64;

    int tid = threadIdx.x;
    int lane = tid & 31;
    int w = tid >> 5;
    int g = lane >> 2;
    int tig = lane & 3;
    const int r0 = w * 16 + g;

    const int jj = lane & 7;
    const uint32_t ldsm_base =
        (uint32_t)((jj + ((lane >> 4) & 1) * 8) * FRS + ((lane >> 3) & 1) * 16);

    const __half* KFg = KF + (size_t)bh * TSEQ * DHEAD;
    const __half* VTg = VT + (size_t)bh * DHEAD * TSEQ;

    {
#pragma unroll
        for (int s = 0; s < 4; s++) {
            int f = tid + s * 128;
            int r = f >> 3;
            int c = (f & 7) * 8;
            uint32_t ro = (uint32_t)(r * FRS + c * 2);
            cp16(smb + OFF_K + ro, KFg + (size_t)r * DHEAD + c);
            cp16(smb + OFF_VT + ro, VTg + (size_t)r * TSEQ + c);
        }
        CP_COMMIT();
    }

    uint32_t qa[4][4];
    {
        const __half* Qg = QF + ((size_t)bh * TSEQ + q0 + r0) * DHEAD;
#pragma unroll
        for (int ks = 0; ks < 4; ks++) {
            int c0 = ks * 16 + 2 * tig;
            qa[ks][0] = *(const uint32_t*)(Qg + c0);
            qa[ks][1] = *(const uint32_t*)(Qg + 8 * DHEAD + c0);
            qa[ks][2] = *(const uint32_t*)(Qg + c0 + 8);
            qa[ks][3] = *(const uint32_t*)(Qg + 8 * DHEAD + c0 + 8);
        }
    }

    float oacc[8][4];
#pragma unroll
    for (int db = 0; db < 8; db++)
#pragma unroll
        for (int r = 0; r < 4; r++) oacc[db][r] = 0.0f;
    float m0 = NEGBIG, m1 = NEGBIG, l0 = 0.0f, l1 = 0.0f;

    for (int jt = 0; jt <= qt; jt++) {
        CP_WAIT0();
        __syncthreads();

        if (jt < qt) {
            int k0n = (jt + 1) * 64;
            uint32_t nb_ = smb + ((jt + 1) & 1) * BUFB;
#pragma unroll
            for (int s = 0; s < 4; s++) {
                int f = tid + s * 128;
                int r = f >> 3;
                int c = (f & 7) * 8;
                uint32_t ro = (uint32_t)(r * FRS + c * 2);
                cp16(nb_ + OFF_K + ro, KFg + (size_t)(k0n + r) * DHEAD + c);
                cp16(nb_ + OFF_VT + ro, VTg + (size_t)r * TSEQ + k0n + c);
            }
            CP_COMMIT();
        }

        const uint32_t bufa = smb + (jt & 1) * BUFB + ldsm_base;

        float sacc[8][4];
#pragma unroll
        for (int nb = 0; nb < 8; nb++)
#pragma unroll
            for (int r = 0; r < 4; r++) sacc[nb][r] = 0.0f;

#pragma unroll
        for (int ks = 0; ks < 4; ks++) {
            const uint32_t ko = (uint32_t)(ks * 32);
#pragma unroll
            for (int nbp = 0; nbp < 4; nbp++) {
                const uint32_t ba = bufa + (uint32_t)(nbp * 16 * FRS) + ko;
                uint32_t b0, b1, b2, b3;
                ldsm_x4(b0, b1, b2, b3, ba + OFF_K);
                mma_fp16(sacc[2 * nbp], qa[ks][0], qa[ks][1], qa[ks][2], qa[ks][3], b0, b1);
                mma_fp16(sacc[2 * nbp + 1], qa[ks][0], qa[ks][1], qa[ks][2], qa[ks][3], b2, b3);
            }
        }

        if (jt == qt) {
#pragma unroll
            for (int nb = 0; nb < 8; nb++) {
                int c0 = nb * 8 + 2 * tig;
#pragma unroll
                for (int e = 0; e < 2; e++) {
                    if (c0 + e > r0) sacc[nb][e] = NEGBIG;
                    if (c0 + e > r0 + 8) sacc[nb][2 + e] = NEGBIG;
                }
            }
        }

        float tm0 = NEGBIG, tm1 = NEGBIG;
#pragma unroll
        for (int nb = 0; nb < 8; nb++) {
            tm0 = fmaxf(tm0, fmaxf(sacc[nb][0], sacc[nb][1]));
            tm1 = fmaxf(tm1, fmaxf(sacc[nb][2], sacc[nb][3]));
        }
        tm0 = fmaxf(tm0, __shfl_xor_sync(0xffffffffu, tm0, 1));
        tm0 = fmaxf(tm0, __shfl_xor_sync(0xffffffffu, tm0, 2));
        tm1 = fmaxf(tm1, __shfl_xor_sync(0xffffffffu, tm1, 1));
        tm1 = fmaxf(tm1, __shfl_xor_sync(0xffffffffu, tm1, 2));

        float mn0 = fmaxf(m0, tm0);
        float mn1 = fmaxf(m1, tm1);
        float corr0 = ex2f(m0 - mn0);
        float corr1 = ex2f(m1 - mn1);
        float rs0 = 0.0f, rs1 = 0.0f;
#pragma unroll
        for (int nb = 0; nb < 8; nb++) {
            sacc[nb][0] = ex2f(sacc[nb][0] - mn0);
            sacc[nb][1] = ex2f(sacc[nb][1] - mn0);
            sacc[nb][2] = ex2f(sacc[nb][2] - mn1);
            sacc[nb][3] = ex2f(sacc[nb][3] - mn1);
            rs0 += sacc[nb][0] + sacc[nb][1];
            rs1 += sacc[nb][2] + sacc[nb][3];
        }
        rs0 += __shfl_xor_sync(0xffffffffu, rs0, 1);
        rs0 += __shfl_xor_sync(0xffffffffu, rs0, 2);
        rs1 += __shfl_xor_sync(0xffffffffu, rs1, 1);
        rs1 += __shfl_xor_sync(0xffffffffu, rs1, 2);

        l0 = l0 * corr0 + rs0;
        l1 = l1 * corr1 + rs1;
        m0 = mn0;
        m1 = mn1;
#pragma unroll
        for (int db = 0; db < 8; db++) {
            oacc[db][0] *= corr0;
            oacc[db][1] *= corr0;
            oacc[db][2] *= corr1;
            oacc[db][3] *= corr1;
        }

#pragma unroll
        for (int ks = 0; ks < 4; ks++) {
            uint32_t p16[4];
            p16[0] = h2u(__floats2half2_rn(sacc[2 * ks][0], sacc[2 * ks][1]));
            p16[1] = h2u(__floats2half2_rn(sacc[2 * ks][2], sacc[2 * ks][3]));
            p16[2] = h2u(__floats2half2_rn(sacc[2 * ks + 1][0], sacc[2 * ks + 1][1]));
            p16[3] = h2u(__floats2half2_rn(sacc[2 * ks + 1][2], sacc[2 * ks + 1][3]));
            const uint32_t ko = (uint32_t)(ks * 32);
#pragma unroll
            for (int dbp = 0; dbp < 4; dbp++) {
                const uint32_t ba = bufa + (uint32_t)(dbp * 16 * FRS) + ko;
                uint32_t v0, v1, v2, v3;
                ldsm_x4(v0, v1, v2, v3, ba + OFF_VT);
                mma_fp16(oacc[2 * dbp], p16[0], p16[1], p16[2], p16[3], v0, v1);
                mma_fp16(oacc[2 * dbp + 1], p16[0], p16[1], p16[2], p16[3], v2, v3);
            }
        }
    }

    // finalize: write y as fp16 A-fragments
    float inv0 = 1.0f / l0;
    float inv1 = 1.0f / l1;
    int b = bh >> 4;
    int h = bh & 15;
    const size_t rb = (size_t)((b * TSEQ + q0) >> 4) + w;
#pragma unroll
    for (int dbp = 0; dbp < 4; dbp++) {
        int cb = h * 4 + dbp;
        uint4 v;
        v.x = h2u(__floats2half2_rn(oacc[2 * dbp][0] * inv0, oacc[2 * dbp][1] * inv0));
        v.y = h2u(__floats2half2_rn(oacc[2 * dbp][2] * inv1, oacc[2 * dbp][3] * inv1));
        v.z = h2u(__floats2half2_rn(oacc[2 * dbp + 1][0] * inv0, oacc[2 * dbp + 1][1] * inv0));
        v.w = h2u(__floats2half2_rn(oacc[2 * dbp + 1][2] * inv1, oacc[2 * dbp + 1][3] * inv1));
        g_yf[(rb * 64 + cb) * 32 + lane] = v;
    }
}

// ---------------------------------------------------------------------------
// Launch
// ---------------------------------------------------------------------------
extern "C" void kernel_launch(void* const* d_in, const int* in_sizes, int n_in,
                              void* d_out, int out_size) {
    const float* x      = (const float*)d_in[0];
    const float* w_attn = (const float*)d_in[1];
    const float* b_attn = (const float*)d_in[2];
    const float* w_proj = (const float*)d_in[3];
    const float* b_proj = (const float*)d_in[4];
    float* out = (float*)d_out;

    uint4 *xf, *waf, *wpf, *yf;
    float2* rope;
    __half *qf, *kf, *vt;
    cudaGetSymbolAddress((void**)&xf, g_xf);
    cudaGetSymbolAddress((void**)&waf, g_waf);
    cudaGetSymbolAddress((void**)&wpf, g_wpf);
    cudaGetSymbolAddress((void**)&yf, g_yf);
    cudaGetSymbolAddress((void**)&qf, g_qf);
    cudaGetSymbolAddress((void**)&kf, g_kf);
    cudaGetSymbolAddress((void**)&vt, g_vt);
    cudaGetSymbolAddress((void**)&rope, g_rope);

    cudaFuncSetAttribute(gemm_fp16_kernel,
                         cudaFuncAttributeMaxDynamicSharedMemorySize,
                         GEMM_SMEM_BYTES);
    cudaFuncSetAttribute(flash_mma_kernel,
                         cudaFuncAttributeMaxDynamicSharedMemorySize,
                         FLASH_SMEM_BYTES);

    build_rope_kernel<<<(TSEQ * 32 + 255) / 256, 256>>>(rope);

    afrag16_kernel<<<(MROWS / 16) * (CDIM / 16) * 32 / 256, 256>>>(x, xf, CDIM);
    bfrag16_kernel<<<(CDIM / 16) * (QKVCOLS / 16) * 32 / 256, 256>>>(w_attn, waf, QKVCOLS);
    bfrag16_kernel<<<(CDIM / 16) * (CDIM / 16) * 32 / 256, 256>>>(w_proj, wpf, CDIM);

    // QKV GEMM with fused RoPE/scatter epilogue
    gemm_fp16_kernel<<<dim3(QKVCOLS / 128, MROWS / 128), 256, GEMM_SMEM_BYTES>>>(
        xf, waf, b_attn, out /*unused*/, MROWS, QKVCOLS, CDIM, 1);

    // Flash attention (writes yf as fp16 A-fragments)
    flash_mma_kernel<<<dim3(TSEQ / 64, BSZ * NHEAD), 128, FLASH_SMEM_BYTES>>>(
        qf, kf, vt);

    // Output projection
    gemm_fp16_kernel<<<dim3(CDIM / 128, MROWS / 128), 256, GEMM_SMEM_BYTES>>>(
        yf, wpf, b_proj, out, MROWS, CDIM, CDIM, 0);
}